// round 8
// baseline (speedup 1.0000x reference)
#include <cuda_runtime.h>
#include <mma.h>
#include <math.h>
#include <stdint.h>

using namespace nvcuda;

// ---------------- problem constants ----------------
#define BATCH   2
#define SEQLEN  2048
#define DMODEL  1024
#define DINNER  2048
#define DSTATE  16
#define DTRANK  64
#define NTOK    (BATCH * SEQLEN)           // 4096
#define XPW     (DTRANK + 2 * DSTATE)      // 96

// ---------------- scratch (device globals; no cudaMalloc allowed) ----------------
__device__ float g_xz[NTOK * 2 * DINNER];        // (4096, 4096): xi | z
__device__ float g_xs[NTOK * DINNER];            // conv+silu output
__device__ float g_xp[NTOK * XPW];               // dt | B | C
__device__ float g_delta[NTOK * DINNER];         // softplus(dt @ W_dt + b_dt)
__device__ float g_y[NTOK * DINNER];             // gated scan output (tf32-rounded)
__device__ float g_part[8 * NTOK * XPW];         // split-K partials for G2
// tf32-pre-rounded GEMM operands
__device__ float g_xr[NTOK * DMODEL];
__device__ float g_winr[DMODEL * 2 * DINNER];
__device__ float g_woutr[DINNER * DMODEL];

// ---------------- helpers ----------------
__device__ __forceinline__ float round_tf32(float v) {
    uint32_t u;
    asm("cvt.rna.tf32.f32 %0, %1;" : "=r"(u) : "f"(v));
    return __uint_as_float(u);
}
__device__ __forceinline__ void cp_async16(void* smem_dst, const void* gmem_src) {
    unsigned saddr = (unsigned)__cvta_generic_to_shared(smem_dst);
    asm volatile("cp.async.cg.shared.global [%0], [%1], 16;\n" :: "r"(saddr), "l"(gmem_src));
}
__device__ __forceinline__ void cp_async_commit() {
    asm volatile("cp.async.commit_group;\n" ::);
}
template <int N>
__device__ __forceinline__ void cp_async_wait() {
    asm volatile("cp.async.wait_group %0;\n" :: "n"(N));
}

// ---------------- tf32 pre-round prepass ----------------
__global__ void round_tf32_kernel(const float4* __restrict__ in,
                                  float4* __restrict__ out, int n4)
{
    const int i = blockIdx.x * blockDim.x + threadIdx.x;
    if (i >= n4) return;
    float4 v = in[i];
    v.x = round_tf32(v.x);
    v.y = round_tf32(v.y);
    v.z = round_tf32(v.z);
    v.w = round_tf32(v.w);
    out[i] = v;
}

// ---------------- TF32 tensor-core GEMM: C(MxN) = A(MxK) @ B(KxN) ----------------
// Row-major A,B pre-rounded to tf32. BM=BN=128, BK=8 per stage, 4 stages,
// 128 threads (4 warps, 2x2 warp grid, warp tile 64x64). One barrier per stage.
// M, N multiples of 128; K multiple of 32.
#define STAGES 4
#define LDA_S  12     // sA row stride (floats): 48B, 16B-aligned, <=2-way conflicts
#define LDB_S  132    // sB row stride (floats): 528B, rows 4 banks apart

__global__ void __launch_bounds__(128, 2)
gemm_tf32(const float* __restrict__ A, int lda,
          const float* __restrict__ B, int ldb,
          float* __restrict__ C, int ldc, int K)
{
    __shared__ float sA[STAGES][128][LDA_S];   // 4*6144  = 24576 B
    __shared__ float sB[STAGES][8][LDB_S];     // 4*4224  = 16896 B

    const int bm  = blockIdx.y * 128;
    const int bn  = blockIdx.x * 128;
    const int tid = threadIdx.x;
    const int warp = tid >> 5;
    const int wr = warp >> 1;          // 0..1 -> 64 rows
    const int wc = warp & 1;           // 0..1 -> 64 cols

    wmma::fragment<wmma::accumulator, 16, 16, 8, float> acc[4][4];
#pragma unroll
    for (int i = 0; i < 4; i++)
#pragma unroll
        for (int j = 0; j < 4; j++) wmma::fill_fragment(acc[i][j], 0.f);

    // load map: A tile 128x8 -> thread t copies row t, 2x16B chunks
    //           B tile 8x128 -> chunk c = t and t+128; row c>>5, col (c&31)*4
    const int b_r0 = tid >> 5;          // 0..3
    const int b_c  = (tid & 31) * 4;

    const int T = K >> 3;               // number of BK=8 stages

    // prologue: stage tiles 0..2
#pragma unroll
    for (int p = 0; p < STAGES - 1; p++) {
        const float* Ag = A + (size_t)(bm + tid) * lda + p * 8;
        cp_async16(&sA[p][tid][0], Ag);
        cp_async16(&sA[p][tid][4], Ag + 4);
        cp_async16(&sB[p][b_r0][b_c],     B + (size_t)(p * 8 + b_r0) * ldb + bn + b_c);
        cp_async16(&sB[p][b_r0 + 4][b_c], B + (size_t)(p * 8 + b_r0 + 4) * ldb + bn + b_c);
        cp_async_commit();
    }

    for (int t = 0; t < T; t++) {
        cp_async_wait<STAGES - 2>();
        __syncthreads();

        // prefetch stage t+3 into buffer (t+3)%4 == (t-1)%4 (all warps are
        // past compute(t-1): program order + the barrier above)
        if (t + STAGES - 1 < T) {
            const int kt = t + STAGES - 1;
            const int st = kt & (STAGES - 1);
            const float* Ag = A + (size_t)(bm + tid) * lda + kt * 8;
            cp_async16(&sA[st][tid][0], Ag);
            cp_async16(&sA[st][tid][4], Ag + 4);
            cp_async16(&sB[st][b_r0][b_c],     B + (size_t)(kt * 8 + b_r0) * ldb + bn + b_c);
            cp_async16(&sB[st][b_r0 + 4][b_c], B + (size_t)(kt * 8 + b_r0 + 4) * ldb + bn + b_c);
        }
        cp_async_commit();   // commit every iter (possibly empty) to keep group count in step

        const int s = t & (STAGES - 1);
        wmma::fragment<wmma::matrix_a, 16, 16, 8, wmma::precision::tf32, wmma::row_major> af[4];
        wmma::fragment<wmma::matrix_b, 16, 16, 8, wmma::precision::tf32, wmma::row_major> bf[4];
#pragma unroll
        for (int i = 0; i < 4; i++)
            wmma::load_matrix_sync(af[i], &sA[s][wr * 64 + i * 16][0], LDA_S);
#pragma unroll
        for (int j = 0; j < 4; j++)
            wmma::load_matrix_sync(bf[j], &sB[s][0][wc * 64 + j * 16], LDB_S);
#pragma unroll
        for (int i = 0; i < 4; i++)
#pragma unroll
            for (int j = 0; j < 4; j++)
                wmma::mma_sync(acc[i][j], af[i], bf[j], acc[i][j]);
    }

#pragma unroll
    for (int i = 0; i < 4; i++)
#pragma unroll
        for (int j = 0; j < 4; j++) {
            float* dst = C + (size_t)(bm + wr * 64 + i * 16) * ldc
                           + bn + wc * 64 + j * 16;
            wmma::store_matrix_sync(dst, acc[i][j], ldc, wmma::mem_row_major);
        }
}

// ---------------- fp32 tiled GEMM (skinny G2 / G3) ----------------
template <int EPI>
__global__ void __launch_bounds__(256, 2)
sgemm128(const float* __restrict__ A, int lda,
         const float* __restrict__ B, int ldb,
         float* __restrict__ C, int ldc,
         int N, int Kslice,
         const float* __restrict__ bias,
         long long c_slice_stride)
{
    __shared__ float sA[8][128];
    __shared__ float sB[8][128];

    const int bm = blockIdx.y * 128;
    const int bn = blockIdx.x * 128;
    const int k0 = blockIdx.z * Kslice;
    C += (long long)blockIdx.z * c_slice_stride;

    const int tid  = threadIdx.x;
    const int arow = tid >> 1;
    const int akc  = (tid & 1) << 2;
    const int brow = tid >> 5;
    const int bcol = (tid & 31) << 2;
    const int tx   = tid & 15;
    const int ty   = tid >> 4;

    float acc[8][8];
#pragma unroll
    for (int i = 0; i < 8; i++)
#pragma unroll
        for (int j = 0; j < 8; j++) acc[i][j] = 0.f;

    const float* Aptr = A + (size_t)(bm + arow) * lda + k0 + akc;
    const float* Bptr = B + (size_t)(k0 + brow) * ldb + bn + bcol;
    const bool bok = (bn + bcol) < N;

    for (int kk = 0; kk < Kslice; kk += 8) {
        float4 av = *reinterpret_cast<const float4*>(Aptr);
        Aptr += 8;
        float4 bv = make_float4(0.f, 0.f, 0.f, 0.f);
        if (bok) bv = *reinterpret_cast<const float4*>(Bptr);
        Bptr += (size_t)8 * ldb;

        sA[akc + 0][arow] = av.x;
        sA[akc + 1][arow] = av.y;
        sA[akc + 2][arow] = av.z;
        sA[akc + 3][arow] = av.w;
        *reinterpret_cast<float4*>(&sB[brow][bcol]) = bv;
        __syncthreads();

#pragma unroll
        for (int p = 0; p < 8; p++) {
            float4 a0 = *reinterpret_cast<const float4*>(&sA[p][ty * 8]);
            float4 a1 = *reinterpret_cast<const float4*>(&sA[p][ty * 8 + 4]);
            float4 b0 = *reinterpret_cast<const float4*>(&sB[p][tx * 8]);
            float4 b1 = *reinterpret_cast<const float4*>(&sB[p][tx * 8 + 4]);
            float ra[8] = {a0.x, a0.y, a0.z, a0.w, a1.x, a1.y, a1.z, a1.w};
            float rb[8] = {b0.x, b0.y, b0.z, b0.w, b1.x, b1.y, b1.z, b1.w};
#pragma unroll
            for (int i = 0; i < 8; i++)
#pragma unroll
                for (int j = 0; j < 8; j++)
                    acc[i][j] = fmaf(ra[i], rb[j], acc[i][j]);
        }
        __syncthreads();
    }

#pragma unroll
    for (int i = 0; i < 8; i++) {
        const int row = bm + ty * 8 + i;
#pragma unroll
        for (int j = 0; j < 8; j++) {
            const int col = bn + tx * 8 + j;
            if (col < N) {
                float v = acc[i][j];
                if (EPI == 1) {
                    v += bias[col];
                    v = (v > 20.f) ? v : log1pf(expf(v));
                }
                C[(size_t)row * ldc + col] = v;
            }
        }
    }
}

// ---------------- depthwise causal conv (k=4) + SiLU ----------------
__global__ void conv_silu_kernel(const float* __restrict__ xz,
                                 const float* __restrict__ cw,
                                 const float* __restrict__ cb,
                                 float* __restrict__ xs)
{
    const int idx = blockIdx.x * blockDim.x + threadIdx.x;
    if (idx >= NTOK * DINNER) return;
    const int d   = idx & (DINNER - 1);
    const int tok = idx >> 11;
    const int l   = tok & (SEQLEN - 1);

    float acc = cb[d];
    const float w0 = cw[d * 4 + 0];
    const float w1 = cw[d * 4 + 1];
    const float w2 = cw[d * 4 + 2];
    const float w3 = cw[d * 4 + 3];
    if (l >= 3) acc += w0 * xz[(size_t)(tok - 3) * (2 * DINNER) + d];
    if (l >= 2) acc += w1 * xz[(size_t)(tok - 2) * (2 * DINNER) + d];
    if (l >= 1) acc += w2 * xz[(size_t)(tok - 1) * (2 * DINNER) + d];
    acc += w3 * xz[(size_t)tok * (2 * DINNER) + d];

    xs[idx] = acc / (1.f + __expf(-acc));
}

// ---------------- split-K reduction (8 slices) ----------------
__global__ void reduce8_kernel(const float* __restrict__ part,
                               float* __restrict__ out, int len)
{
    const int i = blockIdx.x * blockDim.x + threadIdx.x;
    if (i >= len) return;
    float s = 0.f;
#pragma unroll
    for (int k = 0; k < 8; k++) s += part[(size_t)k * len + i];
    out[i] = s;
}

// ---------------- selective scan + skip + gate (emits tf32-rounded y) ----------------
__global__ void __launch_bounds__(128)
scan_kernel(const float* __restrict__ delta,
            const float* __restrict__ xs,
            const float* __restrict__ xp,
            const float* __restrict__ xz,
            const float* __restrict__ A_log,
            const float* __restrict__ Dpar,
            float* __restrict__ y)
{
    const int TT = 128;
    __shared__ float sB[TT][16];
    __shared__ float sC[TT][16];
    __shared__ float sd[TT][8];
    __shared__ float sx[TT][8];
    __shared__ float sz[TT][8];
    __shared__ float so[TT][8];

    const int b    = blockIdx.y;
    const int d0   = blockIdx.x * 8;
    const int tid  = threadIdx.x;
    const int lane = tid & 31;
    const int warp = tid >> 5;
    const int grp  = lane >> 4;
    const int n    = lane & 15;
    const int ch   = warp * 2 + grp;
    const int d    = d0 + ch;

    const float An = -__expf(A_log[d * DSTATE + n]);
    const float Dd = Dpar[d];
    float h = 0.f;

    for (int l0 = 0; l0 < SEQLEN; l0 += TT) {
        for (int i = tid; i < TT * 16; i += 128) {
            const int t = i >> 4, nn = i & 15;
            const float* row = xp + (size_t)(b * SEQLEN + l0 + t) * XPW;
            sB[t][nn] = row[DTRANK + nn];
            sC[t][nn] = row[DTRANK + DSTATE + nn];
        }
        for (int i = tid; i < TT * 8; i += 128) {
            const int t = i >> 3, c = i & 7;
            const size_t tok = (size_t)(b * SEQLEN + l0 + t);
            sd[t][c] = delta[tok * DINNER + d0 + c];
            sx[t][c] = xs[tok * DINNER + d0 + c];
            const float zz = xz[tok * (2 * DINNER) + DINNER + d0 + c];
            sz[t][c] = zz / (1.f + __expf(-zz));
        }
        __syncthreads();

#pragma unroll 4
        for (int t = 0; t < TT; t++) {
            const float dt = sd[t][ch];
            const float xt = sx[t][ch];
            const float dA = __expf(dt * An);
            h = fmaf(dA, h, dt * xt * sB[t][n]);
            float yv = h * sC[t][n];
            yv += __shfl_xor_sync(0xffffffffu, yv, 8);
            yv += __shfl_xor_sync(0xffffffffu, yv, 4);
            yv += __shfl_xor_sync(0xffffffffu, yv, 2);
            yv += __shfl_xor_sync(0xffffffffu, yv, 1);
            if (n == 0) so[t][ch] = round_tf32((yv + Dd * xt) * sz[t][ch]);
        }
        __syncthreads();

        for (int i = tid; i < TT * 8; i += 128) {
            const int t = i >> 3, c = i & 7;
            y[(size_t)(b * SEQLEN + l0 + t) * DINNER + d0 + c] = so[t][c];
        }
    }
}

// ---------------- launcher ----------------
extern "C" void kernel_launch(void* const* d_in, const int* in_sizes, int n_in,
                              void* d_out, int out_size)
{
    const float* x       = (const float*)d_in[0];
    const float* W_in    = (const float*)d_in[1];
    const float* conv_w  = (const float*)d_in[2];
    const float* conv_b  = (const float*)d_in[3];
    const float* W_xproj = (const float*)d_in[4];
    const float* W_dt    = (const float*)d_in[5];
    const float* b_dt    = (const float*)d_in[6];
    const float* A_log   = (const float*)d_in[7];
    const float* Dpar    = (const float*)d_in[8];
    const float* W_out   = (const float*)d_in[9];
    float* out = (float*)d_out;

    float *xz, *xs, *xp, *delta, *y, *part, *xr, *winr, *woutr;
    cudaGetSymbolAddress((void**)&xz,    g_xz);
    cudaGetSymbolAddress((void**)&xs,    g_xs);
    cudaGetSymbolAddress((void**)&xp,    g_xp);
    cudaGetSymbolAddress((void**)&delta, g_delta);
    cudaGetSymbolAddress((void**)&y,     g_y);
    cudaGetSymbolAddress((void**)&part,  g_part);
    cudaGetSymbolAddress((void**)&xr,    g_xr);
    cudaGetSymbolAddress((void**)&winr,  g_winr);
    cudaGetSymbolAddress((void**)&woutr, g_woutr);

    // tf32 pre-round prepass (x, W_in, W_out)
    {
        const int n1 = NTOK * DMODEL / 4;
        round_tf32_kernel<<<(n1 + 255) / 256, 256>>>((const float4*)x, (float4*)xr, n1);
        const int n2 = DMODEL * 2 * DINNER / 4;
        round_tf32_kernel<<<(n2 + 255) / 256, 256>>>((const float4*)W_in, (float4*)winr, n2);
        const int n3 = DINNER * DMODEL / 4;
        round_tf32_kernel<<<(n3 + 255) / 256, 256>>>((const float4*)W_out, (float4*)woutr, n3);
    }

    // G1: xz = x @ W_in  (4096 x 1024) @ (1024 x 4096)  -- TF32 TC multistage
    gemm_tf32<<<dim3((2 * DINNER) / 128, NTOK / 128), 128>>>(
        xr, DMODEL, winr, 2 * DINNER, xz, 2 * DINNER, DMODEL);

    // depthwise causal conv + SiLU -> xs
    conv_silu_kernel<<<(NTOK * DINNER) / 256, 256>>>(xz, conv_w, conv_b, xs);

    // G2 (split-K=8): xp = xs @ W_xproj   (4096 x 2048) @ (2048 x 96)
    sgemm128<0><<<dim3(1, NTOK / 128, 8), 256>>>(
        xs, DINNER, W_xproj, XPW, part, XPW,
        XPW, DINNER / 8, nullptr, (long long)NTOK * XPW);
    reduce8_kernel<<<(NTOK * XPW + 255) / 256, 256>>>(part, xp, NTOK * XPW);

    // G3: delta = softplus(xp[:, :64] @ W_dt + b_dt)   (4096 x 64) @ (64 x 2048)
    sgemm128<1><<<dim3(DINNER / 128, NTOK / 128, 1), 256>>>(
        xp, XPW, W_dt, DINNER, delta, DINNER,
        DINNER, DTRANK, b_dt, 0);

    // selective scan + D*x skip + silu(z) gate -> y (tf32-rounded)
    scan_kernel<<<dim3(DINNER / 8, BATCH), 128>>>(
        delta, xs, xp, xz, A_log, Dpar, y);

    // G4: out = y @ W_out  (4096 x 2048) @ (2048 x 1024)  -- TF32 TC multistage
    gemm_tf32<<<dim3(DMODEL / 128, NTOK / 128), 128>>>(
        y, DINNER, woutr, DMODEL, out, DMODEL, DINNER);
}

// round 10
// speedup vs baseline: 1.9290x; 1.9290x over previous
#include <cuda_runtime.h>
#include <cuda_fp16.h>
#include <math.h>
#include <stdint.h>
#include <mma.h>

using namespace nvcuda;

// ---------------- problem constants ----------------
#define BATCH   2
#define SEQLEN  2048
#define DMODEL  1024
#define DINNER  2048
#define DSTATE  16
#define DTRANK  64
#define NTOK    (BATCH * SEQLEN)           // 4096
#define XPW     (DTRANK + 2 * DSTATE)      // 96

// ---------------- scratch (device globals; no cudaMalloc allowed) ----------------
__device__ float  g_xz[NTOK * 2 * DINNER];       // (4096, 4096): xi | z
__device__ float  g_xs[NTOK * DINNER];           // conv+silu output
__device__ float  g_xp[NTOK * XPW];              // dt | B | C
__device__ float  g_delta[NTOK * DINNER];        // softplus(dt @ W_dt + b_dt)
__device__ float  g_part[8 * NTOK * XPW];        // split-K partials for G2
__device__ __half g_xh[NTOK * DMODEL];           // x in fp16
__device__ __half g_winh[DMODEL * 2 * DINNER];   // W_in in fp16
__device__ __half g_wouth[DINNER * DMODEL];      // W_out in fp16
__device__ __half g_yh[NTOK * DINNER];           // gated scan output in fp16

// ---------------- cp.async helpers ----------------
__device__ __forceinline__ void cp_async16(void* smem_dst, const void* gmem_src) {
    unsigned saddr = (unsigned)__cvta_generic_to_shared(smem_dst);
    asm volatile("cp.async.cg.shared.global [%0], [%1], 16;\n" :: "r"(saddr), "l"(gmem_src));
}
__device__ __forceinline__ void cp_async_commit() {
    asm volatile("cp.async.commit_group;\n" ::);
}
template <int N>
__device__ __forceinline__ void cp_async_wait() {
    asm volatile("cp.async.wait_group %0;\n" :: "n"(N));
}

// ---------------- fp32 -> fp16 convert prepass ----------------
__global__ void f2h_kernel(const float4* __restrict__ in,
                           __half2* __restrict__ out, int n4)
{
    const int i = blockIdx.x * blockDim.x + threadIdx.x;
    if (i >= n4) return;
    float4 v = in[i];
    out[2 * i + 0] = __floats2half2_rn(v.x, v.y);
    out[2 * i + 1] = __floats2half2_rn(v.z, v.w);
}

// ---------------- FP16 tensor-core GEMM: C(MxN) = A(MxK) @ B(KxN) ----------------
// A [M,K], B [K,N] row-major fp16; C fp32. BM=BN=128, BK=16, 3-stage cp.async,
// 128 threads (4 warps, 2x2 grid, warp tile 64x64). One barrier per K-tile.
// M, N multiples of 128; K multiple of 16.
#define LDA_H  24     // sA row stride in halves (48B)
#define LDB_H  136    // sB row stride in halves (272B)

__global__ void __launch_bounds__(128, 2)
gemm_fp16(const __half* __restrict__ A, int lda,
          const __half* __restrict__ B, int ldb,
          float* __restrict__ C, int ldc, int K)
{
    __shared__ __half sA[3][128][LDA_H];   // 3*6144B
    __shared__ __half sB[3][16][LDB_H];    // 3*4352B

    const int bm  = blockIdx.y * 128;
    const int bn  = blockIdx.x * 128;
    const int tid = threadIdx.x;
    const int warp = tid >> 5;
    const int wr = warp >> 1;          // 0..1 -> 64 rows
    const int wc = warp & 1;           // 0..1 -> 64 cols

    wmma::fragment<wmma::accumulator, 16, 16, 16, float> acc[4][4];
#pragma unroll
    for (int i = 0; i < 4; i++)
#pragma unroll
        for (int j = 0; j < 4; j++) wmma::fill_fragment(acc[i][j], 0.f);

    // load maps (128 threads):
    // A tile 128x16 halves: 256 16B-chunks; chunk c -> row c>>1, half-off (c&1)*8
    // B tile 16x128 halves: 256 16B-chunks; chunk c -> row c>>4, col (c&15)*8
    const int a_r0 = tid >> 1;          // rows tid>>1 and +64
    const int a_h  = (tid & 1) * 8;
    const int b_r0 = tid >> 4;          // rows tid>>4 and +8
    const int b_h  = (tid & 15) * 8;

    const int T = K >> 4;

    auto load_stage = [&](int s, int t) {
        const __half* gA = A + (size_t)bm * lda + t * 16;
        cp_async16(&sA[s][a_r0][a_h],      gA + (size_t)a_r0 * lda + a_h);
        cp_async16(&sA[s][a_r0 + 64][a_h], gA + (size_t)(a_r0 + 64) * lda + a_h);
        const __half* gB = B + (size_t)(t * 16) * ldb + bn;
        cp_async16(&sB[s][b_r0][b_h],     gB + (size_t)b_r0 * ldb + b_h);
        cp_async16(&sB[s][b_r0 + 8][b_h], gB + (size_t)(b_r0 + 8) * ldb + b_h);
        cp_async_commit();
    };

    load_stage(0, 0);
    if (T > 1) load_stage(1, 1); else cp_async_commit();

    for (int t = 0; t < T; t++) {
        cp_async_wait<1>();       // tile t complete (t+1 may be in flight)
        __syncthreads();          // single barrier per tile

        if (t + 2 < T) load_stage((t + 2) % 3, t + 2);
        else           cp_async_commit();   // keep group count in step

        const int s = t % 3;
        wmma::fragment<wmma::matrix_a, 16, 16, 16, __half, wmma::row_major> af[4];
        wmma::fragment<wmma::matrix_b, 16, 16, 16, __half, wmma::row_major> bf[4];
#pragma unroll
        for (int i = 0; i < 4; i++)
            wmma::load_matrix_sync(af[i], &sA[s][wr * 64 + i * 16][0], LDA_H);
#pragma unroll
        for (int j = 0; j < 4; j++)
            wmma::load_matrix_sync(bf[j], &sB[s][0][wc * 64 + j * 16], LDB_H);
#pragma unroll
        for (int i = 0; i < 4; i++)
#pragma unroll
            for (int j = 0; j < 4; j++)
                wmma::mma_sync(acc[i][j], af[i], bf[j], acc[i][j]);
    }

#pragma unroll
    for (int i = 0; i < 4; i++)
#pragma unroll
        for (int j = 0; j < 4; j++) {
            float* dst = C + (size_t)(bm + wr * 64 + i * 16) * ldc
                           + bn + wc * 64 + j * 16;
            wmma::store_matrix_sync(dst, acc[i][j], ldc, wmma::mem_row_major);
        }
}

// ---------------- fp32 tiled GEMM (skinny G2 / G3) ----------------
template <int EPI>
__global__ void __launch_bounds__(256, 2)
sgemm128(const float* __restrict__ A, int lda,
         const float* __restrict__ B, int ldb,
         float* __restrict__ C, int ldc,
         int N, int Kslice,
         const float* __restrict__ bias,
         long long c_slice_stride)
{
    __shared__ float sA[8][128];
    __shared__ float sB[8][128];

    const int bm = blockIdx.y * 128;
    const int bn = blockIdx.x * 128;
    const int k0 = blockIdx.z * Kslice;
    C += (long long)blockIdx.z * c_slice_stride;

    const int tid  = threadIdx.x;
    const int arow = tid >> 1;
    const int akc  = (tid & 1) << 2;
    const int brow = tid >> 5;
    const int bcol = (tid & 31) << 2;
    const int tx   = tid & 15;
    const int ty   = tid >> 4;

    float acc[8][8];
#pragma unroll
    for (int i = 0; i < 8; i++)
#pragma unroll
        for (int j = 0; j < 8; j++) acc[i][j] = 0.f;

    const float* Aptr = A + (size_t)(bm + arow) * lda + k0 + akc;
    const float* Bptr = B + (size_t)(k0 + brow) * ldb + bn + bcol;
    const bool bok = (bn + bcol) < N;

    for (int kk = 0; kk < Kslice; kk += 8) {
        float4 av = *reinterpret_cast<const float4*>(Aptr);
        Aptr += 8;
        float4 bv = make_float4(0.f, 0.f, 0.f, 0.f);
        if (bok) bv = *reinterpret_cast<const float4*>(Bptr);
        Bptr += (size_t)8 * ldb;

        sA[akc + 0][arow] = av.x;
        sA[akc + 1][arow] = av.y;
        sA[akc + 2][arow] = av.z;
        sA[akc + 3][arow] = av.w;
        *reinterpret_cast<float4*>(&sB[brow][bcol]) = bv;
        __syncthreads();

#pragma unroll
        for (int p = 0; p < 8; p++) {
            float4 a0 = *reinterpret_cast<const float4*>(&sA[p][ty * 8]);
            float4 a1 = *reinterpret_cast<const float4*>(&sA[p][ty * 8 + 4]);
            float4 b0 = *reinterpret_cast<const float4*>(&sB[p][tx * 8]);
            float4 b1 = *reinterpret_cast<const float4*>(&sB[p][tx * 8 + 4]);
            float ra[8] = {a0.x, a0.y, a0.z, a0.w, a1.x, a1.y, a1.z, a1.w};
            float rb[8] = {b0.x, b0.y, b0.z, b0.w, b1.x, b1.y, b1.z, b1.w};
#pragma unroll
            for (int i = 0; i < 8; i++)
#pragma unroll
                for (int j = 0; j < 8; j++)
                    acc[i][j] = fmaf(ra[i], rb[j], acc[i][j]);
        }
        __syncthreads();
    }

#pragma unroll
    for (int i = 0; i < 8; i++) {
        const int row = bm + ty * 8 + i;
#pragma unroll
        for (int j = 0; j < 8; j++) {
            const int col = bn + tx * 8 + j;
            if (col < N) {
                float v = acc[i][j];
                if (EPI == 1) {
                    v += bias[col];
                    v = (v > 20.f) ? v : log1pf(expf(v));
                }
                C[(size_t)row * ldc + col] = v;
            }
        }
    }
}

// ---------------- depthwise causal conv (k=4) + SiLU ----------------
__global__ void conv_silu_kernel(const float* __restrict__ xz,
                                 const float* __restrict__ cw,
                                 const float* __restrict__ cb,
                                 float* __restrict__ xs)
{
    const int idx = blockIdx.x * blockDim.x + threadIdx.x;
    if (idx >= NTOK * DINNER) return;
    const int d   = idx & (DINNER - 1);
    const int tok = idx >> 11;
    const int l   = tok & (SEQLEN - 1);

    float acc = cb[d];
    const float w0 = cw[d * 4 + 0];
    const float w1 = cw[d * 4 + 1];
    const float w2 = cw[d * 4 + 2];
    const float w3 = cw[d * 4 + 3];
    if (l >= 3) acc += w0 * xz[(size_t)(tok - 3) * (2 * DINNER) + d];
    if (l >= 2) acc += w1 * xz[(size_t)(tok - 2) * (2 * DINNER) + d];
    if (l >= 1) acc += w2 * xz[(size_t)(tok - 1) * (2 * DINNER) + d];
    acc += w3 * xz[(size_t)tok * (2 * DINNER) + d];

    xs[idx] = acc / (1.f + __expf(-acc));
}

// ---------------- split-K reduction (8 slices) ----------------
__global__ void reduce8_kernel(const float* __restrict__ part,
                               float* __restrict__ out, int len)
{
    const int i = blockIdx.x * blockDim.x + threadIdx.x;
    if (i >= len) return;
    float s = 0.f;
#pragma unroll
    for (int k = 0; k < 8; k++) s += part[(size_t)k * len + i];
    out[i] = s;
}

// ---------------- selective scan + skip + gate (emits fp16 y) ----------------
__global__ void __launch_bounds__(128)
scan_kernel(const float* __restrict__ delta,
            const float* __restrict__ xs,
            const float* __restrict__ xp,
            const float* __restrict__ xz,
            const float* __restrict__ A_log,
            const float* __restrict__ Dpar,
            __half* __restrict__ y)
{
    const int TT = 128;
    __shared__ float sB[TT][16];
    __shared__ float sC[TT][16];
    __shared__ float sd[TT][8];
    __shared__ float sx[TT][8];
    __shared__ float sz[TT][8];
    __shared__ float so[TT][8];

    const int b    = blockIdx.y;
    const int d0   = blockIdx.x * 8;
    const int tid  = threadIdx.x;
    const int lane = tid & 31;
    const int warp = tid >> 5;
    const int grp  = lane >> 4;
    const int n    = lane & 15;
    const int ch   = warp * 2 + grp;
    const int d    = d0 + ch;

    const float An = -__expf(A_log[d * DSTATE + n]);
    const float Dd = Dpar[d];
    float h = 0.f;

    for (int l0 = 0; l0 < SEQLEN; l0 += TT) {
        for (int i = tid; i < TT * 16; i += 128) {
            const int t = i >> 4, nn = i & 15;
            const float* row = xp + (size_t)(b * SEQLEN + l0 + t) * XPW;
            sB[t][nn] = row[DTRANK + nn];
            sC[t][nn] = row[DTRANK + DSTATE + nn];
        }
        for (int i = tid; i < TT * 8; i += 128) {
            const int t = i >> 3, c = i & 7;
            const size_t tok = (size_t)(b * SEQLEN + l0 + t);
            sd[t][c] = delta[tok * DINNER + d0 + c];
            sx[t][c] = xs[tok * DINNER + d0 + c];
            const float zz = xz[tok * (2 * DINNER) + DINNER + d0 + c];
            sz[t][c] = zz / (1.f + __expf(-zz));
        }
        __syncthreads();

#pragma unroll 4
        for (int t = 0; t < TT; t++) {
            const float dt = sd[t][ch];
            const float xt = sx[t][ch];
            const float dA = __expf(dt * An);
            h = fmaf(dA, h, dt * xt * sB[t][n]);
            float yv = h * sC[t][n];
            yv += __shfl_xor_sync(0xffffffffu, yv, 8);
            yv += __shfl_xor_sync(0xffffffffu, yv, 4);
            yv += __shfl_xor_sync(0xffffffffu, yv, 2);
            yv += __shfl_xor_sync(0xffffffffu, yv, 1);
            if (n == 0) so[t][ch] = (yv + Dd * xt) * sz[t][ch];
        }
        __syncthreads();

        for (int i = tid; i < TT * 8; i += 128) {
            const int t = i >> 3, c = i & 7;
            y[(size_t)(b * SEQLEN + l0 + t) * DINNER + d0 + c] = __float2half_rn(so[t][c]);
        }
    }
}

// ---------------- launcher ----------------
extern "C" void kernel_launch(void* const* d_in, const int* in_sizes, int n_in,
                              void* d_out, int out_size)
{
    const float* x       = (const float*)d_in[0];
    const float* W_in    = (const float*)d_in[1];
    const float* conv_w  = (const float*)d_in[2];
    const float* conv_b  = (const float*)d_in[3];
    const float* W_xproj = (const float*)d_in[4];
    const float* W_dt    = (const float*)d_in[5];
    const float* b_dt    = (const float*)d_in[6];
    const float* A_log   = (const float*)d_in[7];
    const float* Dpar    = (const float*)d_in[8];
    const float* W_out   = (const float*)d_in[9];
    float* out = (float*)d_out;

    float *xz, *xs, *xp, *delta, *part;
    __half *xh, *winh, *wouth, *yh;
    cudaGetSymbolAddress((void**)&xz,    g_xz);
    cudaGetSymbolAddress((void**)&xs,    g_xs);
    cudaGetSymbolAddress((void**)&xp,    g_xp);
    cudaGetSymbolAddress((void**)&delta, g_delta);
    cudaGetSymbolAddress((void**)&part,  g_part);
    cudaGetSymbolAddress((void**)&xh,    g_xh);
    cudaGetSymbolAddress((void**)&winh,  g_winh);
    cudaGetSymbolAddress((void**)&wouth, g_wouth);
    cudaGetSymbolAddress((void**)&yh,    g_yh);

    // prepass: fp32 -> fp16 (x, W_in, W_out)
    {
        const int n1 = NTOK * DMODEL / 4;
        f2h_kernel<<<(n1 + 255) / 256, 256>>>((const float4*)x, (__half2*)xh, n1);
        const int n2 = DMODEL * 2 * DINNER / 4;
        f2h_kernel<<<(n2 + 255) / 256, 256>>>((const float4*)W_in, (__half2*)winh, n2);
        const int n3 = DINNER * DMODEL / 4;
        f2h_kernel<<<(n3 + 255) / 256, 256>>>((const float4*)W_out, (__half2*)wouth, n3);
    }

    // G1: xz = x @ W_in  (4096x1024)@(1024x4096) -- fp16 TC
    gemm_fp16<<<dim3((2 * DINNER) / 128, NTOK / 128), 128>>>(
        xh, DMODEL, winh, 2 * DINNER, xz, 2 * DINNER, DMODEL);

    // depthwise causal conv + SiLU -> xs
    conv_silu_kernel<<<(NTOK * DINNER) / 256, 256>>>(xz, conv_w, conv_b, xs);

    // G2 (split-K=8): xp = xs @ W_xproj   (4096x2048)@(2048x96)
    sgemm128<0><<<dim3(1, NTOK / 128, 8), 256>>>(
        xs, DINNER, W_xproj, XPW, part, XPW,
        XPW, DINNER / 8, nullptr, (long long)NTOK * XPW);
    reduce8_kernel<<<(NTOK * XPW + 255) / 256, 256>>>(part, xp, NTOK * XPW);

    // G3: delta = softplus(xp[:, :64] @ W_dt + b_dt)   (4096x64)@(64x2048)
    sgemm128<1><<<dim3(DINNER / 128, NTOK / 128, 1), 256>>>(
        xp, XPW, W_dt, DINNER, delta, DINNER,
        DINNER, DTRANK, b_dt, 0);

    // selective scan + D*x skip + silu(z) gate -> yh (fp16)
    scan_kernel<<<dim3(DINNER / 8, BATCH), 128>>>(
        delta, xs, xp, xz, A_log, Dpar, yh);

    // G4: out = y @ W_out  (4096x2048)@(2048x1024) -- fp16 TC
    gemm_fp16<<<dim3(DMODEL / 128, NTOK / 128), 128>>>(
        yh, DINNER, wouth, DMODEL, out, DMODEL, DINNER);
}

// round 11
// speedup vs baseline: 2.3915x; 1.2397x over previous
#include <cuda_runtime.h>
#include <cuda_fp16.h>
#include <math.h>
#include <stdint.h>
#include <mma.h>

using namespace nvcuda;

// ---------------- problem constants ----------------
#define BATCH   2
#define SEQLEN  2048
#define DMODEL  1024
#define DINNER  2048
#define DSTATE  16
#define DTRANK  64
#define NTOK    (BATCH * SEQLEN)           // 4096
#define XPW     (DTRANK + 2 * DSTATE)      // 96

// ---------------- scratch (device globals; no cudaMalloc allowed) ----------------
__device__ float  g_xz[NTOK * 2 * DINNER];       // (4096, 4096): xi | z
__device__ float  g_xs[NTOK * DINNER];           // conv+silu output
__device__ float  g_xp[NTOK * XPW];              // dt | B | C
__device__ float  g_delta[NTOK * DINNER];        // softplus(dt @ W_dt + b_dt)
__device__ float  g_part[8 * NTOK * XPW];        // split-K partials for G2
__device__ __half g_xh[NTOK * DMODEL];           // x in fp16
__device__ __half g_winh[DMODEL * 2 * DINNER];   // W_in in fp16
__device__ __half g_wouth[DINNER * DMODEL];      // W_out in fp16
__device__ __half g_yh[NTOK * DINNER];           // gated scan output in fp16

// ---------------- cp.async helpers ----------------
__device__ __forceinline__ void cp_async16(void* smem_dst, const void* gmem_src) {
    unsigned saddr = (unsigned)__cvta_generic_to_shared(smem_dst);
    asm volatile("cp.async.cg.shared.global [%0], [%1], 16;\n" :: "r"(saddr), "l"(gmem_src));
}
__device__ __forceinline__ void cp_async_commit() {
    asm volatile("cp.async.commit_group;\n" ::);
}
template <int N>
__device__ __forceinline__ void cp_async_wait() {
    asm volatile("cp.async.wait_group %0;\n" :: "n"(N));
}

// ---------------- fp32 -> fp16 convert prepass ----------------
__global__ void f2h_kernel(const float4* __restrict__ in,
                           __half2* __restrict__ out, int n4)
{
    const int i = blockIdx.x * blockDim.x + threadIdx.x;
    if (i >= n4) return;
    float4 v = in[i];
    out[2 * i + 0] = __floats2half2_rn(v.x, v.y);
    out[2 * i + 1] = __floats2half2_rn(v.z, v.w);
}

// ---------------- FP16 tensor-core GEMM: C(MxN) = A(MxK) @ B(KxN) ----------------
// A [M,K], B [K,N] row-major fp16; C fp32. BM=BN=128, BK=16, 3-stage cp.async,
// 128 threads (4 warps, 2x2 grid, warp tile 64x64). One barrier per K-tile.
#define LDA_H  24     // sA row stride in halves (48B)
#define LDB_H  136    // sB row stride in halves (272B)

__global__ void __launch_bounds__(128, 2)
gemm_fp16(const __half* __restrict__ A, int lda,
          const __half* __restrict__ B, int ldb,
          float* __restrict__ C, int ldc, int K)
{
    __shared__ __half sA[3][128][LDA_H];
    __shared__ __half sB[3][16][LDB_H];

    const int bm  = blockIdx.y * 128;
    const int bn  = blockIdx.x * 128;
    const int tid = threadIdx.x;
    const int warp = tid >> 5;
    const int wr = warp >> 1;
    const int wc = warp & 1;

    wmma::fragment<wmma::accumulator, 16, 16, 16, float> acc[4][4];
#pragma unroll
    for (int i = 0; i < 4; i++)
#pragma unroll
        for (int j = 0; j < 4; j++) wmma::fill_fragment(acc[i][j], 0.f);

    const int a_r0 = tid >> 1;
    const int a_h  = (tid & 1) * 8;
    const int b_r0 = tid >> 4;
    const int b_h  = (tid & 15) * 8;

    const int T = K >> 4;

    auto load_stage = [&](int s, int t) {
        const __half* gA = A + (size_t)bm * lda + t * 16;
        cp_async16(&sA[s][a_r0][a_h],      gA + (size_t)a_r0 * lda + a_h);
        cp_async16(&sA[s][a_r0 + 64][a_h], gA + (size_t)(a_r0 + 64) * lda + a_h);
        const __half* gB = B + (size_t)(t * 16) * ldb + bn;
        cp_async16(&sB[s][b_r0][b_h],     gB + (size_t)b_r0 * ldb + b_h);
        cp_async16(&sB[s][b_r0 + 8][b_h], gB + (size_t)(b_r0 + 8) * ldb + b_h);
        cp_async_commit();
    };

    load_stage(0, 0);
    if (T > 1) load_stage(1, 1); else cp_async_commit();

    for (int t = 0; t < T; t++) {
        cp_async_wait<1>();
        __syncthreads();

        if (t + 2 < T) load_stage((t + 2) % 3, t + 2);
        else           cp_async_commit();

        const int s = t % 3;
        wmma::fragment<wmma::matrix_a, 16, 16, 16, __half, wmma::row_major> af[4];
        wmma::fragment<wmma::matrix_b, 16, 16, 16, __half, wmma::row_major> bf[4];
#pragma unroll
        for (int i = 0; i < 4; i++)
            wmma::load_matrix_sync(af[i], &sA[s][wr * 64 + i * 16][0], LDA_H);
#pragma unroll
        for (int j = 0; j < 4; j++)
            wmma::load_matrix_sync(bf[j], &sB[s][0][wc * 64 + j * 16], LDB_H);
#pragma unroll
        for (int i = 0; i < 4; i++)
#pragma unroll
            for (int j = 0; j < 4; j++)
                wmma::mma_sync(acc[i][j], af[i], bf[j], acc[i][j]);
    }

#pragma unroll
    for (int i = 0; i < 4; i++)
#pragma unroll
        for (int j = 0; j < 4; j++) {
            float* dst = C + (size_t)(bm + wr * 64 + i * 16) * ldc
                           + bn + wc * 64 + j * 16;
            wmma::store_matrix_sync(dst, acc[i][j], ldc, wmma::mem_row_major);
        }
}

// ---------------- fp32 tiled GEMM (skinny G2 / G3) ----------------
template <int EPI>
__global__ void __launch_bounds__(256, 2)
sgemm128(const float* __restrict__ A, int lda,
         const float* __restrict__ B, int ldb,
         float* __restrict__ C, int ldc,
         int N, int Kslice,
         const float* __restrict__ bias,
         long long c_slice_stride)
{
    __shared__ float sA[8][128];
    __shared__ float sB[8][128];

    const int bm = blockIdx.y * 128;
    const int bn = blockIdx.x * 128;
    const int k0 = blockIdx.z * Kslice;
    C += (long long)blockIdx.z * c_slice_stride;

    const int tid  = threadIdx.x;
    const int arow = tid >> 1;
    const int akc  = (tid & 1) << 2;
    const int brow = tid >> 5;
    const int bcol = (tid & 31) << 2;
    const int tx   = tid & 15;
    const int ty   = tid >> 4;

    float acc[8][8];
#pragma unroll
    for (int i = 0; i < 8; i++)
#pragma unroll
        for (int j = 0; j < 8; j++) acc[i][j] = 0.f;

    const float* Aptr = A + (size_t)(bm + arow) * lda + k0 + akc;
    const float* Bptr = B + (size_t)(k0 + brow) * ldb + bn + bcol;
    const bool bok = (bn + bcol) < N;

    for (int kk = 0; kk < Kslice; kk += 8) {
        float4 av = *reinterpret_cast<const float4*>(Aptr);
        Aptr += 8;
        float4 bv = make_float4(0.f, 0.f, 0.f, 0.f);
        if (bok) bv = *reinterpret_cast<const float4*>(Bptr);
        Bptr += (size_t)8 * ldb;

        sA[akc + 0][arow] = av.x;
        sA[akc + 1][arow] = av.y;
        sA[akc + 2][arow] = av.z;
        sA[akc + 3][arow] = av.w;
        *reinterpret_cast<float4*>(&sB[brow][bcol]) = bv;
        __syncthreads();

#pragma unroll
        for (int p = 0; p < 8; p++) {
            float4 a0 = *reinterpret_cast<const float4*>(&sA[p][ty * 8]);
            float4 a1 = *reinterpret_cast<const float4*>(&sA[p][ty * 8 + 4]);
            float4 b0 = *reinterpret_cast<const float4*>(&sB[p][tx * 8]);
            float4 b1 = *reinterpret_cast<const float4*>(&sB[p][tx * 8 + 4]);
            float ra[8] = {a0.x, a0.y, a0.z, a0.w, a1.x, a1.y, a1.z, a1.w};
            float rb[8] = {b0.x, b0.y, b0.z, b0.w, b1.x, b1.y, b1.z, b1.w};
#pragma unroll
            for (int i = 0; i < 8; i++)
#pragma unroll
                for (int j = 0; j < 8; j++)
                    acc[i][j] = fmaf(ra[i], rb[j], acc[i][j]);
        }
        __syncthreads();
    }

#pragma unroll
    for (int i = 0; i < 8; i++) {
        const int row = bm + ty * 8 + i;
#pragma unroll
        for (int j = 0; j < 8; j++) {
            const int col = bn + tx * 8 + j;
            if (col < N) {
                float v = acc[i][j];
                if (EPI == 1) {
                    v += bias[col];
                    v = (v > 20.f) ? v : log1pf(expf(v));
                }
                C[(size_t)row * ldc + col] = v;
            }
        }
    }
}

// ---------------- depthwise causal conv (k=4) + SiLU ----------------
__global__ void conv_silu_kernel(const float* __restrict__ xz,
                                 const float* __restrict__ cw,
                                 const float* __restrict__ cb,
                                 float* __restrict__ xs)
{
    const int idx = blockIdx.x * blockDim.x + threadIdx.x;
    if (idx >= NTOK * DINNER) return;
    const int d   = idx & (DINNER - 1);
    const int tok = idx >> 11;
    const int l   = tok & (SEQLEN - 1);

    float acc = cb[d];
    const float w0 = cw[d * 4 + 0];
    const float w1 = cw[d * 4 + 1];
    const float w2 = cw[d * 4 + 2];
    const float w3 = cw[d * 4 + 3];
    if (l >= 3) acc += w0 * xz[(size_t)(tok - 3) * (2 * DINNER) + d];
    if (l >= 2) acc += w1 * xz[(size_t)(tok - 2) * (2 * DINNER) + d];
    if (l >= 1) acc += w2 * xz[(size_t)(tok - 1) * (2 * DINNER) + d];
    acc += w3 * xz[(size_t)tok * (2 * DINNER) + d];

    xs[idx] = acc / (1.f + __expf(-acc));
}

// ---------------- split-K reduction (8 slices) ----------------
__global__ void reduce8_kernel(const float* __restrict__ part,
                               float* __restrict__ out, int len)
{
    const int i = blockIdx.x * blockDim.x + threadIdx.x;
    if (i >= len) return;
    float s = 0.f;
#pragma unroll
    for (int k = 0; k < 8; k++) s += part[(size_t)k * len + i];
    out[i] = s;
}

// ---------------- selective scan + skip + gate (shuffle-free) ----------------
// 16 lanes = 16 states of one channel, 2 channels/warp, 8 channels/block.
// Scan loop stores h*C[n] to smem (4-cyc fma chain only); a separate
// throughput pass reduces 16 states per (t, channel) and writes gated fp16 y.
#define STT 32                       // time tile
#define HCP 17                       // padded per-channel stride (bank-conflict-free)

__global__ void __launch_bounds__(128)
scan_kernel(const float* __restrict__ delta,
            const float* __restrict__ xs,
            const float* __restrict__ xp,
            const float* __restrict__ xz,
            const float* __restrict__ A_log,
            const float* __restrict__ Dpar,
            __half* __restrict__ y)
{
    __shared__ float sB[STT][16];
    __shared__ float sC[STT][16];
    __shared__ float sd[STT][8];
    __shared__ float sx[STT][8];
    __shared__ float sz[STT][8];
    __shared__ float sHC[STT][8 * HCP];
    __shared__ float sDp[8];

    const int b    = blockIdx.y;
    const int d0   = blockIdx.x * 8;
    const int tid  = threadIdx.x;
    const int lane = tid & 31;
    const int warp = tid >> 5;
    const int grp  = lane >> 4;
    const int n    = lane & 15;
    const int ch   = warp * 2 + grp;
    const int d    = d0 + ch;

    const float An = -__expf(A_log[d * DSTATE + n]);
    if (tid < 8) sDp[tid] = Dpar[d0 + tid];
    float h = 0.f;

    for (int l0 = 0; l0 < SEQLEN; l0 += STT) {
        // stage B/C (per-batch) and delta/x/silu(z) (per-channel)
#pragma unroll
        for (int i = tid; i < STT * 16; i += 128) {
            const int t = i >> 4, nn = i & 15;
            const float* row = xp + (size_t)(b * SEQLEN + l0 + t) * XPW;
            sB[t][nn] = row[DTRANK + nn];
            sC[t][nn] = row[DTRANK + DSTATE + nn];
        }
#pragma unroll
        for (int i = tid; i < STT * 8; i += 128) {
            const int t = i >> 3, c = i & 7;
            const size_t tok = (size_t)(b * SEQLEN + l0 + t);
            sd[t][c] = delta[tok * DINNER + d0 + c];
            sx[t][c] = xs[tok * DINNER + d0 + c];
            const float zz = xz[tok * (2 * DINNER) + DINNER + d0 + c];
            sz[t][c] = zz / (1.f + __expf(-zz));
        }
        __syncthreads();

        // scan: only carried dependency is the 4-cycle fma on h
#pragma unroll 8
        for (int t = 0; t < STT; t++) {
            const float dt = sd[t][ch];
            const float xt = sx[t][ch];
            const float dA = __expf(dt * An);
            h = fmaf(dA, h, dt * xt * sB[t][n]);
            sHC[t][ch * HCP + n] = h * sC[t][n];
        }
        __syncthreads();

        // reduce 16 states per (t, channel), apply skip + gate, write fp16 y
#pragma unroll
        for (int o = tid; o < STT * 8; o += 128) {
            const int t = o >> 3, c = o & 7;
            const float* p = &sHC[t][c * HCP];
            float s = 0.f;
#pragma unroll
            for (int j = 0; j < 16; j++) s += p[j];
            const float val = (s + sDp[c] * sx[t][c]) * sz[t][c];
            y[(size_t)(b * SEQLEN + l0 + t) * DINNER + d0 + c] = __float2half_rn(val);
        }
        __syncthreads();   // protect sx/sz/sHC before next tile's staging
    }
}

// ---------------- launcher ----------------
extern "C" void kernel_launch(void* const* d_in, const int* in_sizes, int n_in,
                              void* d_out, int out_size)
{
    const float* x       = (const float*)d_in[0];
    const float* W_in    = (const float*)d_in[1];
    const float* conv_w  = (const float*)d_in[2];
    const float* conv_b  = (const float*)d_in[3];
    const float* W_xproj = (const float*)d_in[4];
    const float* W_dt    = (const float*)d_in[5];
    const float* b_dt    = (const float*)d_in[6];
    const float* A_log   = (const float*)d_in[7];
    const float* Dpar    = (const float*)d_in[8];
    const float* W_out   = (const float*)d_in[9];
    float* out = (float*)d_out;

    float *xz, *xs, *xp, *delta, *part;
    __half *xh, *winh, *wouth, *yh;
    cudaGetSymbolAddress((void**)&xz,    g_xz);
    cudaGetSymbolAddress((void**)&xs,    g_xs);
    cudaGetSymbolAddress((void**)&xp,    g_xp);
    cudaGetSymbolAddress((void**)&delta, g_delta);
    cudaGetSymbolAddress((void**)&part,  g_part);
    cudaGetSymbolAddress((void**)&xh,    g_xh);
    cudaGetSymbolAddress((void**)&winh,  g_winh);
    cudaGetSymbolAddress((void**)&wouth, g_wouth);
    cudaGetSymbolAddress((void**)&yh,    g_yh);

    // prepass: fp32 -> fp16 (x, W_in, W_out)
    {
        const int n1 = NTOK * DMODEL / 4;
        f2h_kernel<<<(n1 + 255) / 256, 256>>>((const float4*)x, (__half2*)xh, n1);
        const int n2 = DMODEL * 2 * DINNER / 4;
        f2h_kernel<<<(n2 + 255) / 256, 256>>>((const float4*)W_in, (__half2*)winh, n2);
        const int n3 = DINNER * DMODEL / 4;
        f2h_kernel<<<(n3 + 255) / 256, 256>>>((const float4*)W_out, (__half2*)wouth, n3);
    }

    // G1: xz = x @ W_in  (4096x1024)@(1024x4096) -- fp16 TC
    gemm_fp16<<<dim3((2 * DINNER) / 128, NTOK / 128), 128>>>(
        xh, DMODEL, winh, 2 * DINNER, xz, 2 * DINNER, DMODEL);

    // depthwise causal conv + SiLU -> xs
    conv_silu_kernel<<<(NTOK * DINNER) / 256, 256>>>(xz, conv_w, conv_b, xs);

    // G2 (split-K=8): xp = xs @ W_xproj   (4096x2048)@(2048x96)
    sgemm128<0><<<dim3(1, NTOK / 128, 8), 256>>>(
        xs, DINNER, W_xproj, XPW, part, XPW,
        XPW, DINNER / 8, nullptr, (long long)NTOK * XPW);
    reduce8_kernel<<<(NTOK * XPW + 255) / 256, 256>>>(part, xp, NTOK * XPW);

    // G3: delta = softplus(xp[:, :64] @ W_dt + b_dt)   (4096x64)@(64x2048)
    sgemm128<1><<<dim3(DINNER / 128, NTOK / 128, 1), 256>>>(
        xp, XPW, W_dt, DINNER, delta, DINNER,
        DINNER, DTRANK, b_dt, 0);

    // selective scan + D*x skip + silu(z) gate -> yh (fp16)
    scan_kernel<<<dim3(DINNER / 8, BATCH), 128>>>(
        delta, xs, xp, xz, A_log, Dpar, yh);

    // G4: out = y @ W_out  (4096x2048)@(2048x1024) -- fp16 TC
    gemm_fp16<<<dim3(DMODEL / 128, NTOK / 128), 128>>>(
        yh, DINNER, wouth, DMODEL, out, DMODEL, DINNER);
}

// round 12
// speedup vs baseline: 2.4972x; 1.0442x over previous
#include <cuda_runtime.h>
#include <cuda_fp16.h>
#include <math.h>
#include <stdint.h>
#include <mma.h>

using namespace nvcuda;

// ---------------- problem constants ----------------
#define BATCH   2
#define SEQLEN  2048
#define DMODEL  1024
#define DINNER  2048
#define DSTATE  16
#define DTRANK  64
#define NTOK    (BATCH * SEQLEN)           // 4096
#define XPW     (DTRANK + 2 * DSTATE)      // 96

// ---------------- scratch (device globals; no cudaMalloc allowed) ----------------
__device__ float  g_xz[NTOK * 2 * DINNER];       // (4096, 4096): xi | z
__device__ float  g_xs[NTOK * DINNER];           // conv+silu output
__device__ float  g_xp[NTOK * XPW];              // dt | B | C
__device__ float  g_delta[NTOK * DINNER];        // softplus(dt @ W_dt + b_dt)
__device__ float  g_part[8 * NTOK * XPW];        // split-K partials for G2
__device__ __half g_xh[NTOK * DMODEL];           // x in fp16
__device__ __half g_winh[DMODEL * 2 * DINNER];   // W_in in fp16
__device__ __half g_wouth[DINNER * DMODEL];      // W_out in fp16
__device__ __half g_yh[NTOK * DINNER];           // gated scan output in fp16

// ---------------- cp.async helpers ----------------
__device__ __forceinline__ void cp_async16(void* smem_dst, const void* gmem_src) {
    unsigned saddr = (unsigned)__cvta_generic_to_shared(smem_dst);
    asm volatile("cp.async.cg.shared.global [%0], [%1], 16;\n" :: "r"(saddr), "l"(gmem_src));
}
__device__ __forceinline__ void cp_async_commit() {
    asm volatile("cp.async.commit_group;\n" ::);
}
template <int N>
__device__ __forceinline__ void cp_async_wait() {
    asm volatile("cp.async.wait_group %0;\n" :: "n"(N));
}

// ---------------- fp32 -> fp16 convert prepass ----------------
__global__ void f2h_kernel(const float4* __restrict__ in,
                           __half2* __restrict__ out, int n4)
{
    const int i = blockIdx.x * blockDim.x + threadIdx.x;
    if (i >= n4) return;
    float4 v = in[i];
    out[2 * i + 0] = __floats2half2_rn(v.x, v.y);
    out[2 * i + 1] = __floats2half2_rn(v.z, v.w);
}

// ---------------- FP16 tensor-core GEMM: C(MxN) = A(MxK) @ B(KxN) ----------------
// A [M,K], B [K,N] row-major fp16; C fp32. BM=BN=128, BK=16, 3-stage cp.async,
// 256 threads (8 warps, 4x2 grid, warp tile 32x64). One barrier per K-tile.
#define LDA_H  24     // sA row stride in halves (48B)
#define LDB_H  136    // sB row stride in halves (272B)

__global__ void __launch_bounds__(256, 2)
gemm_fp16(const __half* __restrict__ A, int lda,
          const __half* __restrict__ B, int ldb,
          float* __restrict__ C, int ldc, int K)
{
    __shared__ __half sA[3][128][LDA_H];
    __shared__ __half sB[3][16][LDB_H];

    const int bm  = blockIdx.y * 128;
    const int bn  = blockIdx.x * 128;
    const int tid = threadIdx.x;
    const int warp = tid >> 5;
    const int wr = warp >> 1;          // 0..3 -> 32-row strips
    const int wc = warp & 1;           // 0..1 -> 64-col strips

    wmma::fragment<wmma::accumulator, 16, 16, 16, float> acc[2][4];
#pragma unroll
    for (int i = 0; i < 2; i++)
#pragma unroll
        for (int j = 0; j < 4; j++) wmma::fill_fragment(acc[i][j], 0.f);

    // load maps (256 threads, 1 chunk each):
    const int a_r = tid >> 1;           // 0..127
    const int a_h = (tid & 1) * 8;
    const int b_r = tid >> 4;           // 0..15
    const int b_h = (tid & 15) * 8;

    const int T = K >> 4;

    auto load_stage = [&](int s, int t) {
        cp_async16(&sA[s][a_r][a_h], A + (size_t)(bm + a_r) * lda + t * 16 + a_h);
        cp_async16(&sB[s][b_r][b_h], B + (size_t)(t * 16 + b_r) * ldb + bn + b_h);
        cp_async_commit();
    };

    load_stage(0, 0);
    if (T > 1) load_stage(1, 1); else cp_async_commit();

    for (int t = 0; t < T; t++) {
        cp_async_wait<1>();
        __syncthreads();

        if (t + 2 < T) load_stage((t + 2) % 3, t + 2);
        else           cp_async_commit();

        const int s = t % 3;
        wmma::fragment<wmma::matrix_a, 16, 16, 16, __half, wmma::row_major> af[2];
        wmma::fragment<wmma::matrix_b, 16, 16, 16, __half, wmma::row_major> bf[4];
#pragma unroll
        for (int i = 0; i < 2; i++)
            wmma::load_matrix_sync(af[i], &sA[s][wr * 32 + i * 16][0], LDA_H);
#pragma unroll
        for (int j = 0; j < 4; j++)
            wmma::load_matrix_sync(bf[j], &sB[s][0][wc * 64 + j * 16], LDB_H);
#pragma unroll
        for (int i = 0; i < 2; i++)
#pragma unroll
            for (int j = 0; j < 4; j++)
                wmma::mma_sync(acc[i][j], af[i], bf[j], acc[i][j]);
    }

#pragma unroll
    for (int i = 0; i < 2; i++)
#pragma unroll
        for (int j = 0; j < 4; j++) {
            float* dst = C + (size_t)(bm + wr * 32 + i * 16) * ldc
                           + bn + wc * 64 + j * 16;
            wmma::store_matrix_sync(dst, acc[i][j], ldc, wmma::mem_row_major);
        }
}

// ---------------- fp32 tiled GEMM (skinny G2 / G3) ----------------
template <int EPI>
__global__ void __launch_bounds__(256, 2)
sgemm128(const float* __restrict__ A, int lda,
         const float* __restrict__ B, int ldb,
         float* __restrict__ C, int ldc,
         int N, int Kslice,
         const float* __restrict__ bias,
         long long c_slice_stride)
{
    __shared__ float sA[8][128];
    __shared__ float sB[8][128];

    const int bm = blockIdx.y * 128;
    const int bn = blockIdx.x * 128;
    const int k0 = blockIdx.z * Kslice;
    C += (long long)blockIdx.z * c_slice_stride;

    const int tid  = threadIdx.x;
    const int arow = tid >> 1;
    const int akc  = (tid & 1) << 2;
    const int brow = tid >> 5;
    const int bcol = (tid & 31) << 2;
    const int tx   = tid & 15;
    const int ty   = tid >> 4;

    float acc[8][8];
#pragma unroll
    for (int i = 0; i < 8; i++)
#pragma unroll
        for (int j = 0; j < 8; j++) acc[i][j] = 0.f;

    const float* Aptr = A + (size_t)(bm + arow) * lda + k0 + akc;
    const float* Bptr = B + (size_t)(k0 + brow) * ldb + bn + bcol;
    const bool bok = (bn + bcol) < N;

    for (int kk = 0; kk < Kslice; kk += 8) {
        float4 av = *reinterpret_cast<const float4*>(Aptr);
        Aptr += 8;
        float4 bv = make_float4(0.f, 0.f, 0.f, 0.f);
        if (bok) bv = *reinterpret_cast<const float4*>(Bptr);
        Bptr += (size_t)8 * ldb;

        sA[akc + 0][arow] = av.x;
        sA[akc + 1][arow] = av.y;
        sA[akc + 2][arow] = av.z;
        sA[akc + 3][arow] = av.w;
        *reinterpret_cast<float4*>(&sB[brow][bcol]) = bv;
        __syncthreads();

#pragma unroll
        for (int p = 0; p < 8; p++) {
            float4 a0 = *reinterpret_cast<const float4*>(&sA[p][ty * 8]);
            float4 a1 = *reinterpret_cast<const float4*>(&sA[p][ty * 8 + 4]);
            float4 b0 = *reinterpret_cast<const float4*>(&sB[p][tx * 8]);
            float4 b1 = *reinterpret_cast<const float4*>(&sB[p][tx * 8 + 4]);
            float ra[8] = {a0.x, a0.y, a0.z, a0.w, a1.x, a1.y, a1.z, a1.w};
            float rb[8] = {b0.x, b0.y, b0.z, b0.w, b1.x, b1.y, b1.z, b1.w};
#pragma unroll
            for (int i = 0; i < 8; i++)
#pragma unroll
                for (int j = 0; j < 8; j++)
                    acc[i][j] = fmaf(ra[i], rb[j], acc[i][j]);
        }
        __syncthreads();
    }

#pragma unroll
    for (int i = 0; i < 8; i++) {
        const int row = bm + ty * 8 + i;
#pragma unroll
        for (int j = 0; j < 8; j++) {
            const int col = bn + tx * 8 + j;
            if (col < N) {
                float v = acc[i][j];
                if (EPI == 1) {
                    v += bias[col];
                    v = (v > 20.f) ? v : log1pf(expf(v));
                }
                C[(size_t)row * ldc + col] = v;
            }
        }
    }
}

// ---------------- depthwise causal conv (k=4) + SiLU ----------------
__global__ void conv_silu_kernel(const float* __restrict__ xz,
                                 const float* __restrict__ cw,
                                 const float* __restrict__ cb,
                                 float* __restrict__ xs)
{
    const int idx = blockIdx.x * blockDim.x + threadIdx.x;
    if (idx >= NTOK * DINNER) return;
    const int d   = idx & (DINNER - 1);
    const int tok = idx >> 11;
    const int l   = tok & (SEQLEN - 1);

    float acc = cb[d];
    const float w0 = cw[d * 4 + 0];
    const float w1 = cw[d * 4 + 1];
    const float w2 = cw[d * 4 + 2];
    const float w3 = cw[d * 4 + 3];
    if (l >= 3) acc += w0 * xz[(size_t)(tok - 3) * (2 * DINNER) + d];
    if (l >= 2) acc += w1 * xz[(size_t)(tok - 2) * (2 * DINNER) + d];
    if (l >= 1) acc += w2 * xz[(size_t)(tok - 1) * (2 * DINNER) + d];
    acc += w3 * xz[(size_t)tok * (2 * DINNER) + d];

    xs[idx] = acc / (1.f + __expf(-acc));
}

// ---------------- split-K reduction (8 slices) ----------------
__global__ void reduce8_kernel(const float* __restrict__ part,
                               float* __restrict__ out, int len)
{
    const int i = blockIdx.x * blockDim.x + threadIdx.x;
    if (i >= len) return;
    float s = 0.f;
#pragma unroll
    for (int k = 0; k < 8; k++) s += part[(size_t)k * len + i];
    out[i] = s;
}

// ---------------- selective scan + skip + gate (cp.async double-buffered) ----------------
// 16 lanes = 16 states of one channel, 2 channels/warp, 8 channels/block.
// Tile t+1 staged via cp.async while tile t computes. Scan stores h*C to smem;
// reduction pass sums 16 states, applies skip + silu(z) gate, writes fp16 y.
#define STT 32                       // time tile
#define HCP 17                       // padded per-channel stride

__global__ void __launch_bounds__(128)
scan_kernel(const float* __restrict__ delta,
            const float* __restrict__ xs,
            const float* __restrict__ xp,
            const float* __restrict__ xz,
            const float* __restrict__ A_log,
            const float* __restrict__ Dpar,
            __half* __restrict__ y)
{
    __shared__ float sB[2][STT][16];
    __shared__ float sC[2][STT][16];
    __shared__ float sd[2][STT][8];
    __shared__ float sx[2][STT][8];
    __shared__ float szr[2][STT][8];     // raw z (silu applied in reduce pass)
    __shared__ float sHC[STT][8 * HCP];
    __shared__ float sDp[8];

    const int b    = blockIdx.y;
    const int d0   = blockIdx.x * 8;
    const int tid  = threadIdx.x;
    const int lane = tid & 31;
    const int warp = tid >> 5;
    const int grp  = lane >> 4;
    const int n    = lane & 15;
    const int ch   = warp * 2 + grp;
    const int d    = d0 + ch;

    const float An = -__expf(A_log[d * DSTATE + n]);
    if (tid < 8) sDp[tid] = Dpar[d0 + tid];
    float h = 0.f;

    const int T = SEQLEN / STT;

    // cp.async staging of one tile into buffer `buf`
    auto stage = [&](int buf, int l0) {
        // B/C: 8 16B-chunks per time-step (4 B + 4 C), 256 total
#pragma unroll
        for (int i = tid; i < STT * 8; i += 128) {
            const int t = i >> 3, j = i & 7;
            const float* row = xp + (size_t)(b * SEQLEN + l0 + t) * XPW + DTRANK;
            if (j < 4) cp_async16(&sB[buf][t][j * 4], row + j * 4);
            else       cp_async16(&sC[buf][t][(j - 4) * 4], row + DSTATE + (j - 4) * 4);
        }
        // delta / xs / raw z: 2 chunks each per time-step
#pragma unroll
        for (int i = tid; i < STT * 2; i += 128) {
            const int t = i >> 1, c4 = (i & 1) * 4;
            const size_t tok = (size_t)(b * SEQLEN + l0 + t);
            cp_async16(&sd[buf][t][c4],  delta + tok * DINNER + d0 + c4);
            cp_async16(&sx[buf][t][c4],  xs    + tok * DINNER + d0 + c4);
            cp_async16(&szr[buf][t][c4], xz + tok * (2 * DINNER) + DINNER + d0 + c4);
        }
    };

    stage(0, 0);
    cp_async_commit();

    for (int ti = 0; ti < T; ti++) {
        if (ti + 1 < T) stage((ti + 1) & 1, (ti + 1) * STT);
        cp_async_commit();              // keep group count in step

        cp_async_wait<1>();             // tile ti complete
        __syncthreads();

        const int buf = ti & 1;
        const int l0  = ti * STT;

        // scan: only carried dependency is the 4-cycle fma on h
#pragma unroll 8
        for (int t = 0; t < STT; t++) {
            const float dt = sd[buf][t][ch];
            const float xt = sx[buf][t][ch];
            const float dA = __expf(dt * An);
            h = fmaf(dA, h, dt * xt * sB[buf][t][n]);
            sHC[t][ch * HCP + n] = h * sC[buf][t][n];
        }
        __syncthreads();

        // reduce 16 states per (t, channel), apply skip + gate, write fp16 y
#pragma unroll
        for (int o = tid; o < STT * 8; o += 128) {
            const int t = o >> 3, c = o & 7;
            const float* p = &sHC[t][c * HCP];
            float s = 0.f;
#pragma unroll
            for (int j = 0; j < 16; j++) s += p[j];
            const float zz = szr[buf][t][c];
            const float zs = zz / (1.f + __expf(-zz));
            const float val = (s + sDp[c] * sx[buf][t][c]) * zs;
            y[(size_t)(b * SEQLEN + l0 + t) * DINNER + d0 + c] = __float2half_rn(val);
        }
        __syncthreads();   // buf reusable; sHC protected
    }
}

// ---------------- launcher ----------------
extern "C" void kernel_launch(void* const* d_in, const int* in_sizes, int n_in,
                              void* d_out, int out_size)
{
    const float* x       = (const float*)d_in[0];
    const float* W_in    = (const float*)d_in[1];
    const float* conv_w  = (const float*)d_in[2];
    const float* conv_b  = (const float*)d_in[3];
    const float* W_xproj = (const float*)d_in[4];
    const float* W_dt    = (const float*)d_in[5];
    const float* b_dt    = (const float*)d_in[6];
    const float* A_log   = (const float*)d_in[7];
    const float* Dpar    = (const float*)d_in[8];
    const float* W_out   = (const float*)d_in[9];
    float* out = (float*)d_out;

    float *xz, *xs, *xp, *delta, *part;
    __half *xh, *winh, *wouth, *yh;
    cudaGetSymbolAddress((void**)&xz,    g_xz);
    cudaGetSymbolAddress((void**)&xs,    g_xs);
    cudaGetSymbolAddress((void**)&xp,    g_xp);
    cudaGetSymbolAddress((void**)&delta, g_delta);
    cudaGetSymbolAddress((void**)&part,  g_part);
    cudaGetSymbolAddress((void**)&xh,    g_xh);
    cudaGetSymbolAddress((void**)&winh,  g_winh);
    cudaGetSymbolAddress((void**)&wouth, g_wouth);
    cudaGetSymbolAddress((void**)&yh,    g_yh);

    // prepass: fp32 -> fp16 (x, W_in, W_out)
    {
        const int n1 = NTOK * DMODEL / 4;
        f2h_kernel<<<(n1 + 255) / 256, 256>>>((const float4*)x, (__half2*)xh, n1);
        const int n2 = DMODEL * 2 * DINNER / 4;
        f2h_kernel<<<(n2 + 255) / 256, 256>>>((const float4*)W_in, (__half2*)winh, n2);
        const int n3 = DINNER * DMODEL / 4;
        f2h_kernel<<<(n3 + 255) / 256, 256>>>((const float4*)W_out, (__half2*)wouth, n3);
    }

    // G1: xz = x @ W_in  (4096x1024)@(1024x4096) -- fp16 TC
    gemm_fp16<<<dim3((2 * DINNER) / 128, NTOK / 128), 256>>>(
        xh, DMODEL, winh, 2 * DINNER, xz, 2 * DINNER, DMODEL);

    // depthwise causal conv + SiLU -> xs
    conv_silu_kernel<<<(NTOK * DINNER) / 256, 256>>>(xz, conv_w, conv_b, xs);

    // G2 (split-K=8): xp = xs @ W_xproj   (4096x2048)@(2048x96)
    sgemm128<0><<<dim3(1, NTOK / 128, 8), 256>>>(
        xs, DINNER, W_xproj, XPW, part, XPW,
        XPW, DINNER / 8, nullptr, (long long)NTOK * XPW);
    reduce8_kernel<<<(NTOK * XPW + 255) / 256, 256>>>(part, xp, NTOK * XPW);

    // G3: delta = softplus(xp[:, :64] @ W_dt + b_dt)   (4096x64)@(64x2048)
    sgemm128<1><<<dim3(DINNER / 128, NTOK / 128, 1), 256>>>(
        xp, XPW, W_dt, DINNER, delta, DINNER,
        DINNER, DTRANK, b_dt, 0);

    // selective scan + D*x skip + silu(z) gate -> yh (fp16)
    scan_kernel<<<dim3(DINNER / 8, BATCH), 128>>>(
        delta, xs, xp, xz, A_log, Dpar, yh);

    // G4: out = y @ W_out  (4096x2048)@(2048x1024) -- fp16 TC
    gemm_fp16<<<dim3(DMODEL / 128, NTOK / 128), 256>>>(
        yh, DINNER, wouth, DMODEL, out, DMODEL, DINNER);
}

// round 13
// speedup vs baseline: 2.5581x; 1.0244x over previous
#include <cuda_runtime.h>
#include <cuda_fp16.h>
#include <math.h>
#include <stdint.h>
#include <mma.h>

using namespace nvcuda;

// ---------------- problem constants ----------------
#define BATCH   2
#define SEQLEN  2048
#define DMODEL  1024
#define DINNER  2048
#define DSTATE  16
#define DTRANK  64
#define NTOK    (BATCH * SEQLEN)           // 4096
#define XPW     (DTRANK + 2 * DSTATE)      // 96

// ---------------- scratch (device globals; no cudaMalloc allowed) ----------------
__device__ float  g_xz[NTOK * 2 * DINNER];       // (4096, 4096): xi | z
__device__ float  g_xs[NTOK * DINNER];           // conv+silu output
__device__ float  g_xp[NTOK * XPW];              // dt | B | C
__device__ float  g_delta[NTOK * DINNER];        // softplus(dt @ W_dt + b_dt)
__device__ float  g_part[8 * NTOK * XPW];        // split-K partials for G2
__device__ __half g_xh[NTOK * DMODEL];           // x in fp16
__device__ __half g_winh[DMODEL * 2 * DINNER];   // W_in in fp16
__device__ __half g_wouth[DINNER * DMODEL];      // W_out in fp16
__device__ __half g_yh[NTOK * DINNER];           // gated scan output in fp16

// ---------------- cp.async helpers ----------------
__device__ __forceinline__ void cp_async16(void* smem_dst, const void* gmem_src) {
    unsigned saddr = (unsigned)__cvta_generic_to_shared(smem_dst);
    asm volatile("cp.async.cg.shared.global [%0], [%1], 16;\n" :: "r"(saddr), "l"(gmem_src));
}
__device__ __forceinline__ void cp_async_commit() {
    asm volatile("cp.async.commit_group;\n" ::);
}
template <int N>
__device__ __forceinline__ void cp_async_wait() {
    asm volatile("cp.async.wait_group %0;\n" :: "n"(N));
}

// ---------------- fp32 -> fp16 convert prepass ----------------
__global__ void f2h_kernel(const float4* __restrict__ in,
                           __half2* __restrict__ out, int n4)
{
    const int i = blockIdx.x * blockDim.x + threadIdx.x;
    if (i >= n4) return;
    float4 v = in[i];
    out[2 * i + 0] = __floats2half2_rn(v.x, v.y);
    out[2 * i + 1] = __floats2half2_rn(v.z, v.w);
}

// ---------------- FP16 tensor-core GEMM: C(MxN) = A(MxK) @ B(KxN) ----------------
// A [M,K], B [K,N] row-major fp16; C fp32. BM=BN=128, 128 threads (4 warps,
// 2x2 grid, warp tile 64x64). 6-stage BK=16 ring processed in PAIRS:
// one wait_group + one barrier per 32 K-elements, one commit group per pair.
#define LDA_H  24     // sA row stride in halves (48B)
#define LDB_H  136    // sB row stride in halves (272B)
#define A_STG  (128 * LDA_H)   // halves per A stage (3072)
#define B_STG  (16 * LDB_H)    // halves per B stage (2176)
// dynamic smem: 6 A stages + 6 B stages = 6*(3072+2176)*2 = 62976 B
#define GEMM_SMEM ((6 * (A_STG + B_STG)) * (int)sizeof(__half))

__global__ void __launch_bounds__(128, 2)
gemm_fp16(const __half* __restrict__ A, int lda,
          const __half* __restrict__ B, int ldb,
          float* __restrict__ C, int ldc, int K)
{
    extern __shared__ __half smem[];
    __half* sA = smem;                  // [6][128][LDA_H]
    __half* sB = smem + 6 * A_STG;      // [6][16][LDB_H]

    const int bm  = blockIdx.y * 128;
    const int bn  = blockIdx.x * 128;
    const int tid = threadIdx.x;
    const int warp = tid >> 5;
    const int wr = warp >> 1;
    const int wc = warp & 1;

    wmma::fragment<wmma::accumulator, 16, 16, 16, float> acc[4][4];
#pragma unroll
    for (int i = 0; i < 4; i++)
#pragma unroll
        for (int j = 0; j < 4; j++) wmma::fill_fragment(acc[i][j], 0.f);

    // per-thread load coordinates (128 threads; 2 A chunks + 2 B chunks per tile)
    const int a_r0 = tid >> 1;          // rows tid>>1 and +64
    const int a_h  = (tid & 1) * 8;
    const int b_r0 = tid >> 4;          // rows tid>>4 and +8
    const int b_h  = (tid & 15) * 8;

    const int P = K >> 5;               // number of BK=32 pairs (K mult of 32)

    // load one PAIR of BK=16 tiles (tiles 2q, 2q+1) into stages 2*(q%3), +1;
    // single commit group per pair.
    auto load_pair = [&](int q) {
        const int s0 = 2 * (q % 3);
#pragma unroll
        for (int u = 0; u < 2; u++) {
            const int t = 2 * q + u;
            __half* dA = sA + (s0 + u) * A_STG;
            __half* dB = sB + (s0 + u) * B_STG;
            const __half* gA = A + (size_t)bm * lda + t * 16;
            cp_async16(dA + a_r0 * LDA_H + a_h,        gA + (size_t)a_r0 * lda + a_h);
            cp_async16(dA + (a_r0 + 64) * LDA_H + a_h, gA + (size_t)(a_r0 + 64) * lda + a_h);
            const __half* gB = B + (size_t)(t * 16) * ldb + bn;
            cp_async16(dB + b_r0 * LDB_H + b_h,       gB + (size_t)b_r0 * ldb + b_h);
            cp_async16(dB + (b_r0 + 8) * LDB_H + b_h, gB + (size_t)(b_r0 + 8) * ldb + b_h);
        }
        cp_async_commit();
    };

    load_pair(0);
    load_pair(1);

    for (int p = 0; p < P; p++) {
        cp_async_wait<1>();   // pair p complete (pair p+1 may be in flight)
        __syncthreads();      // all warps past pair p-1 compute

        // prefetch pair p+2 into pair p-1's stages (freed by the barrier)
        if (p + 2 < P) load_pair(p + 2);
        else           cp_async_commit();   // keep group count in step

        const int s0 = 2 * (p % 3);
#pragma unroll
        for (int u = 0; u < 2; u++) {
            const __half* tA = sA + (s0 + u) * A_STG;
            const __half* tB = sB + (s0 + u) * B_STG;
            wmma::fragment<wmma::matrix_a, 16, 16, 16, __half, wmma::row_major> af[4];
            wmma::fragment<wmma::matrix_b, 16, 16, 16, __half, wmma::row_major> bf[4];
#pragma unroll
            for (int i = 0; i < 4; i++)
                wmma::load_matrix_sync(af[i], tA + (wr * 64 + i * 16) * LDA_H, LDA_H);
#pragma unroll
            for (int j = 0; j < 4; j++)
                wmma::load_matrix_sync(bf[j], tB + wc * 64 + j * 16, LDB_H);
#pragma unroll
            for (int i = 0; i < 4; i++)
#pragma unroll
                for (int j = 0; j < 4; j++)
                    wmma::mma_sync(acc[i][j], af[i], bf[j], acc[i][j]);
        }
    }

#pragma unroll
    for (int i = 0; i < 4; i++)
#pragma unroll
        for (int j = 0; j < 4; j++) {
            float* dst = C + (size_t)(bm + wr * 64 + i * 16) * ldc
                           + bn + wc * 64 + j * 16;
            wmma::store_matrix_sync(dst, acc[i][j], ldc, wmma::mem_row_major);
        }
}

// ---------------- fp32 tiled GEMM (skinny G2 / G3) ----------------
template <int EPI>
__global__ void __launch_bounds__(256, 2)
sgemm128(const float* __restrict__ A, int lda,
         const float* __restrict__ B, int ldb,
         float* __restrict__ C, int ldc,
         int N, int Kslice,
         const float* __restrict__ bias,
         long long c_slice_stride)
{
    __shared__ float sA[8][128];
    __shared__ float sB[8][128];

    const int bm = blockIdx.y * 128;
    const int bn = blockIdx.x * 128;
    const int k0 = blockIdx.z * Kslice;
    C += (long long)blockIdx.z * c_slice_stride;

    const int tid  = threadIdx.x;
    const int arow = tid >> 1;
    const int akc  = (tid & 1) << 2;
    const int brow = tid >> 5;
    const int bcol = (tid & 31) << 2;
    const int tx   = tid & 15;
    const int ty   = tid >> 4;

    float acc[8][8];
#pragma unroll
    for (int i = 0; i < 8; i++)
#pragma unroll
        for (int j = 0; j < 8; j++) acc[i][j] = 0.f;

    const float* Aptr = A + (size_t)(bm + arow) * lda + k0 + akc;
    const float* Bptr = B + (size_t)(k0 + brow) * ldb + bn + bcol;
    const bool bok = (bn + bcol) < N;

    for (int kk = 0; kk < Kslice; kk += 8) {
        float4 av = *reinterpret_cast<const float4*>(Aptr);
        Aptr += 8;
        float4 bv = make_float4(0.f, 0.f, 0.f, 0.f);
        if (bok) bv = *reinterpret_cast<const float4*>(Bptr);
        Bptr += (size_t)8 * ldb;

        sA[akc + 0][arow] = av.x;
        sA[akc + 1][arow] = av.y;
        sA[akc + 2][arow] = av.z;
        sA[akc + 3][arow] = av.w;
        *reinterpret_cast<float4*>(&sB[brow][bcol]) = bv;
        __syncthreads();

#pragma unroll
        for (int p = 0; p < 8; p++) {
            float4 a0 = *reinterpret_cast<const float4*>(&sA[p][ty * 8]);
            float4 a1 = *reinterpret_cast<const float4*>(&sA[p][ty * 8 + 4]);
            float4 b0 = *reinterpret_cast<const float4*>(&sB[p][tx * 8]);
            float4 b1 = *reinterpret_cast<const float4*>(&sB[p][tx * 8 + 4]);
            float ra[8] = {a0.x, a0.y, a0.z, a0.w, a1.x, a1.y, a1.z, a1.w};
            float rb[8] = {b0.x, b0.y, b0.z, b0.w, b1.x, b1.y, b1.z, b1.w};
#pragma unroll
            for (int i = 0; i < 8; i++)
#pragma unroll
                for (int j = 0; j < 8; j++)
                    acc[i][j] = fmaf(ra[i], rb[j], acc[i][j]);
        }
        __syncthreads();
    }

#pragma unroll
    for (int i = 0; i < 8; i++) {
        const int row = bm + ty * 8 + i;
#pragma unroll
        for (int j = 0; j < 8; j++) {
            const int col = bn + tx * 8 + j;
            if (col < N) {
                float v = acc[i][j];
                if (EPI == 1) {
                    v += bias[col];
                    v = (v > 20.f) ? v : log1pf(expf(v));
                }
                C[(size_t)row * ldc + col] = v;
            }
        }
    }
}

// ---------------- depthwise causal conv (k=4) + SiLU ----------------
__global__ void conv_silu_kernel(const float* __restrict__ xz,
                                 const float* __restrict__ cw,
                                 const float* __restrict__ cb,
                                 float* __restrict__ xs)
{
    const int idx = blockIdx.x * blockDim.x + threadIdx.x;
    if (idx >= NTOK * DINNER) return;
    const int d   = idx & (DINNER - 1);
    const int tok = idx >> 11;
    const int l   = tok & (SEQLEN - 1);

    float acc = cb[d];
    const float w0 = cw[d * 4 + 0];
    const float w1 = cw[d * 4 + 1];
    const float w2 = cw[d * 4 + 2];
    const float w3 = cw[d * 4 + 3];
    if (l >= 3) acc += w0 * xz[(size_t)(tok - 3) * (2 * DINNER) + d];
    if (l >= 2) acc += w1 * xz[(size_t)(tok - 2) * (2 * DINNER) + d];
    if (l >= 1) acc += w2 * xz[(size_t)(tok - 1) * (2 * DINNER) + d];
    acc += w3 * xz[(size_t)tok * (2 * DINNER) + d];

    xs[idx] = acc / (1.f + __expf(-acc));
}

// ---------------- split-K reduction (8 slices) ----------------
__global__ void reduce8_kernel(const float* __restrict__ part,
                               float* __restrict__ out, int len)
{
    const int i = blockIdx.x * blockDim.x + threadIdx.x;
    if (i >= len) return;
    float s = 0.f;
#pragma unroll
    for (int k = 0; k < 8; k++) s += part[(size_t)k * len + i];
    out[i] = s;
}

// ---------------- selective scan + skip + gate (cp.async double-buffered) ----------------
#define STT 32                       // time tile
#define HCP 17                       // padded per-channel stride (conflict-free)

__global__ void __launch_bounds__(128)
scan_kernel(const float* __restrict__ delta,
            const float* __restrict__ xs,
            const float* __restrict__ xp,
            const float* __restrict__ xz,
            const float* __restrict__ A_log,
            const float* __restrict__ Dpar,
            __half* __restrict__ y)
{
    __shared__ float sB[2][STT][16];
    __shared__ float sC[2][STT][16];
    __shared__ float sd[2][STT][8];
    __shared__ float sx[2][STT][8];
    __shared__ float szr[2][STT][8];     // raw z (silu in reduce pass)
    __shared__ float sHC[STT][8 * HCP];
    __shared__ float sDp[8];

    const int b    = blockIdx.y;
    const int d0   = blockIdx.x * 8;
    const int tid  = threadIdx.x;
    const int lane = tid & 31;
    const int warp = tid >> 5;
    const int grp  = lane >> 4;
    const int n    = lane & 15;
    const int ch   = warp * 2 + grp;
    const int d    = d0 + ch;

    const float An = -__expf(A_log[d * DSTATE + n]);
    if (tid < 8) sDp[tid] = Dpar[d0 + tid];
    float h = 0.f;

    const int T = SEQLEN / STT;

    auto stage = [&](int buf, int l0) {
#pragma unroll
        for (int i = tid; i < STT * 8; i += 128) {
            const int t = i >> 3, j = i & 7;
            const float* row = xp + (size_t)(b * SEQLEN + l0 + t) * XPW + DTRANK;
            if (j < 4) cp_async16(&sB[buf][t][j * 4], row + j * 4);
            else       cp_async16(&sC[buf][t][(j - 4) * 4], row + DSTATE + (j - 4) * 4);
        }
#pragma unroll
        for (int i = tid; i < STT * 2; i += 128) {
            const int t = i >> 1, c4 = (i & 1) * 4;
            const size_t tok = (size_t)(b * SEQLEN + l0 + t);
            cp_async16(&sd[buf][t][c4],  delta + tok * DINNER + d0 + c4);
            cp_async16(&sx[buf][t][c4],  xs    + tok * DINNER + d0 + c4);
            cp_async16(&szr[buf][t][c4], xz + tok * (2 * DINNER) + DINNER + d0 + c4);
        }
    };

    stage(0, 0);
    cp_async_commit();

    for (int ti = 0; ti < T; ti++) {
        if (ti + 1 < T) stage((ti + 1) & 1, (ti + 1) * STT);
        cp_async_commit();

        cp_async_wait<1>();
        __syncthreads();

        const int buf = ti & 1;
        const int l0  = ti * STT;

#pragma unroll 8
        for (int t = 0; t < STT; t++) {
            const float dt = sd[buf][t][ch];
            const float xt = sx[buf][t][ch];
            const float dA = __expf(dt * An);
            h = fmaf(dA, h, dt * xt * sB[buf][t][n]);
            sHC[t][ch * HCP + n] = h * sC[buf][t][n];
        }
        __syncthreads();

#pragma unroll
        for (int o = tid; o < STT * 8; o += 128) {
            const int t = o >> 3, c = o & 7;
            const float* p = &sHC[t][c * HCP];
            float s = 0.f;
#pragma unroll
            for (int j = 0; j < 16; j++) s += p[j];
            const float zz = szr[buf][t][c];
            const float zs = zz / (1.f + __expf(-zz));
            const float val = (s + sDp[c] * sx[buf][t][c]) * zs;
            y[(size_t)(b * SEQLEN + l0 + t) * DINNER + d0 + c] = __float2half_rn(val);
        }
        __syncthreads();
    }
}

// ---------------- launcher ----------------
extern "C" void kernel_launch(void* const* d_in, const int* in_sizes, int n_in,
                              void* d_out, int out_size)
{
    const float* x       = (const float*)d_in[0];
    const float* W_in    = (const float*)d_in[1];
    const float* conv_w  = (const float*)d_in[2];
    const float* conv_b  = (const float*)d_in[3];
    const float* W_xproj = (const float*)d_in[4];
    const float* W_dt    = (const float*)d_in[5];
    const float* b_dt    = (const float*)d_in[6];
    const float* A_log   = (const float*)d_in[7];
    const float* Dpar    = (const float*)d_in[8];
    const float* W_out   = (const float*)d_in[9];
    float* out = (float*)d_out;

    float *xz, *xs, *xp, *delta, *part;
    __half *xh, *winh, *wouth, *yh;
    cudaGetSymbolAddress((void**)&xz,    g_xz);
    cudaGetSymbolAddress((void**)&xs,    g_xs);
    cudaGetSymbolAddress((void**)&xp,    g_xp);
    cudaGetSymbolAddress((void**)&delta, g_delta);
    cudaGetSymbolAddress((void**)&part,  g_part);
    cudaGetSymbolAddress((void**)&xh,    g_xh);
    cudaGetSymbolAddress((void**)&winh,  g_winh);
    cudaGetSymbolAddress((void**)&wouth, g_wouth);
    cudaGetSymbolAddress((void**)&yh,    g_yh);

    cudaFuncSetAttribute(gemm_fp16, cudaFuncAttributeMaxDynamicSharedMemorySize, GEMM_SMEM);

    // prepass: fp32 -> fp16 (x, W_in, W_out)
    {
        const int n1 = NTOK * DMODEL / 4;
        f2h_kernel<<<(n1 + 255) / 256, 256>>>((const float4*)x, (__half2*)xh, n1);
        const int n2 = DMODEL * 2 * DINNER / 4;
        f2h_kernel<<<(n2 + 255) / 256, 256>>>((const float4*)W_in, (__half2*)winh, n2);
        const int n3 = DINNER * DMODEL / 4;
        f2h_kernel<<<(n3 + 255) / 256, 256>>>((const float4*)W_out, (__half2*)wouth, n3);
    }

    // G1: xz = x @ W_in  (4096x1024)@(1024x4096) -- fp16 TC
    gemm_fp16<<<dim3((2 * DINNER) / 128, NTOK / 128), 128, GEMM_SMEM>>>(
        xh, DMODEL, winh, 2 * DINNER, xz, 2 * DINNER, DMODEL);

    // depthwise causal conv + SiLU -> xs
    conv_silu_kernel<<<(NTOK * DINNER) / 256, 256>>>(xz, conv_w, conv_b, xs);

    // G2 (split-K=8): xp = xs @ W_xproj   (4096x2048)@(2048x96)
    sgemm128<0><<<dim3(1, NTOK / 128, 8), 256>>>(
        xs, DINNER, W_xproj, XPW, part, XPW,
        XPW, DINNER / 8, nullptr, (long long)NTOK * XPW);
    reduce8_kernel<<<(NTOK * XPW + 255) / 256, 256>>>(part, xp, NTOK * XPW);

    // G3: delta = softplus(xp[:, :64] @ W_dt + b_dt)   (4096x64)@(64x2048)
    sgemm128<1><<<dim3(DINNER / 128, NTOK / 128, 1), 256>>>(
        xp, XPW, W_dt, DINNER, delta, DINNER,
        DINNER, DTRANK, b_dt, 0);

    // selective scan + D*x skip + silu(z) gate -> yh (fp16)
    scan_kernel<<<dim3(DINNER / 8, BATCH), 128>>>(
        delta, xs, xp, xz, A_log, Dpar, yh);

    // G4: out = y @ W_out  (4096x2048)@(2048x1024) -- fp16 TC
    gemm_fp16<<<dim3(DMODEL / 128, NTOK / 128), 128, GEMM_SMEM>>>(
        yh, DINNER, wouth, DMODEL, out, DMODEL, DINNER);
}

// round 14
// speedup vs baseline: 3.0142x; 1.1783x over previous
#include <cuda_runtime.h>
#include <cuda_fp16.h>
#include <math.h>
#include <stdint.h>
#include <mma.h>

using namespace nvcuda;

// ---------------- problem constants ----------------
#define BATCH   2
#define SEQLEN  2048
#define DMODEL  1024
#define DINNER  2048
#define DSTATE  16
#define DTRANK  64
#define NTOK    (BATCH * SEQLEN)           // 4096
#define XPW     96                         // logical width of xproj output
#define XPP     128                        // padded width (fp16 TC friendly)

// ---------------- scratch (device globals; no cudaMalloc allowed) ----------------
__device__ float  g_xz[NTOK * 2 * DINNER];       // (4096, 4096): xi | z
__device__ float  g_xs[NTOK * DINNER];           // conv+silu output (fp32, scan)
__device__ __half g_xsh[NTOK * DINNER];          // conv+silu output (fp16, G2)
__device__ float  g_xp[NTOK * XPP];              // dt | B | C (padded to 128)
__device__ __half g_xph[NTOK * DTRANK];          // dt columns in fp16 (G3 A)
__device__ float  g_delta[NTOK * DINNER];        // softplus(dt @ W_dt + b_dt)
__device__ float  g_part[8 * NTOK * XPP];        // split-K partials for G2
__device__ __half g_xh[NTOK * DMODEL];           // x in fp16
__device__ __half g_winh[DMODEL * 2 * DINNER];   // W_in in fp16
__device__ __half g_wouth[DINNER * DMODEL];      // W_out in fp16
__device__ __half g_wxh[DINNER * XPP];           // W_xproj fp16, zero-padded to 128
__device__ __half g_wdth[DTRANK * DINNER];       // W_dt in fp16
__device__ __half g_yh[NTOK * DINNER];           // gated scan output in fp16

// ---------------- cp.async helpers ----------------
__device__ __forceinline__ void cp_async16(void* smem_dst, const void* gmem_src) {
    unsigned saddr = (unsigned)__cvta_generic_to_shared(smem_dst);
    asm volatile("cp.async.cg.shared.global [%0], [%1], 16;\n" :: "r"(saddr), "l"(gmem_src));
}
__device__ __forceinline__ void cp_async_commit() {
    asm volatile("cp.async.commit_group;\n" ::);
}
template <int N>
__device__ __forceinline__ void cp_async_wait() {
    asm volatile("cp.async.wait_group %0;\n" :: "n"(N));
}

// ---------------- prepass kernels ----------------
__global__ void f2h_kernel(const float4* __restrict__ in,
                           __half2* __restrict__ out, int n4)
{
    const int i = blockIdx.x * blockDim.x + threadIdx.x;
    if (i >= n4) return;
    float4 v = in[i];
    out[2 * i + 0] = __floats2half2_rn(v.x, v.y);
    out[2 * i + 1] = __floats2half2_rn(v.z, v.w);
}

// W_xproj [2048,96] fp32 -> [2048,128] fp16 zero-padded
__global__ void padw_kernel(const float* __restrict__ w, __half* __restrict__ o)
{
    const int i = blockIdx.x * blockDim.x + threadIdx.x;
    if (i >= DINNER * XPP) return;
    const int r = i >> 7, c = i & 127;
    o[i] = (c < XPW) ? __float2half_rn(w[r * XPW + c]) : __float2half_rn(0.f);
}

// ---------------- FP16 tensor-core GEMM (R10 config + split-K + epilogue) ----------
// C(MxN) = A(MxK) @ B(KxN), row-major fp16 in / fp32 out. BM=BN=128, BK=16,
// 3-stage cp.async ring, 128 threads (4 warps, 2x2, warp tile 64x64).
// blockIdx.z slices K (Kslice per slice, C += z*c_slice_stride).
// EPI==1: C = softplus(acc + bias[col]).
#define LDA_H  24
#define LDB_H  136

template <int EPI>
__global__ void __launch_bounds__(128, 2)
gemm_h(const __half* __restrict__ A, int lda,
       const __half* __restrict__ B, int ldb,
       float* __restrict__ C, int ldc, int Kslice,
       const float* __restrict__ bias, long long c_slice_stride)
{
    __shared__ __half sA[3][128][LDA_H];
    __shared__ __half sB[3][16][LDB_H];

    const int bm  = blockIdx.y * 128;
    const int bn  = blockIdx.x * 128;
    const int tid = threadIdx.x;
    const int warp = tid >> 5;
    const int wr = warp >> 1;
    const int wc = warp & 1;

    A += blockIdx.z * Kslice;                      // K offset into A cols
    B += (size_t)blockIdx.z * Kslice * ldb;        // K offset into B rows
    C += (long long)blockIdx.z * c_slice_stride;

    wmma::fragment<wmma::accumulator, 16, 16, 16, float> acc[4][4];
#pragma unroll
    for (int i = 0; i < 4; i++)
#pragma unroll
        for (int j = 0; j < 4; j++) wmma::fill_fragment(acc[i][j], 0.f);

    const int a_r0 = tid >> 1;
    const int a_h  = (tid & 1) * 8;
    const int b_r0 = tid >> 4;
    const int b_h  = (tid & 15) * 8;

    const int T = Kslice >> 4;

    auto load_stage = [&](int s, int t) {
        const __half* gA = A + (size_t)bm * lda + t * 16;
        cp_async16(&sA[s][a_r0][a_h],      gA + (size_t)a_r0 * lda + a_h);
        cp_async16(&sA[s][a_r0 + 64][a_h], gA + (size_t)(a_r0 + 64) * lda + a_h);
        const __half* gB = B + (size_t)(t * 16) * ldb + bn;
        cp_async16(&sB[s][b_r0][b_h],     gB + (size_t)b_r0 * ldb + b_h);
        cp_async16(&sB[s][b_r0 + 8][b_h], gB + (size_t)(b_r0 + 8) * ldb + b_h);
        cp_async_commit();
    };

    load_stage(0, 0);
    if (T > 1) load_stage(1, 1); else cp_async_commit();

    for (int t = 0; t < T; t++) {
        cp_async_wait<1>();
        __syncthreads();

        if (t + 2 < T) load_stage((t + 2) % 3, t + 2);
        else           cp_async_commit();

        const int s = t % 3;
        wmma::fragment<wmma::matrix_a, 16, 16, 16, __half, wmma::row_major> af[4];
        wmma::fragment<wmma::matrix_b, 16, 16, 16, __half, wmma::row_major> bf[4];
#pragma unroll
        for (int i = 0; i < 4; i++)
            wmma::load_matrix_sync(af[i], &sA[s][wr * 64 + i * 16][0], LDA_H);
#pragma unroll
        for (int j = 0; j < 4; j++)
            wmma::load_matrix_sync(bf[j], &sB[s][0][wc * 64 + j * 16], LDB_H);
#pragma unroll
        for (int i = 0; i < 4; i++)
#pragma unroll
            for (int j = 0; j < 4; j++)
                wmma::mma_sync(acc[i][j], af[i], bf[j], acc[i][j]);
    }

    if (EPI == 0) {
#pragma unroll
        for (int i = 0; i < 4; i++)
#pragma unroll
            for (int j = 0; j < 4; j++) {
                float* dst = C + (size_t)(bm + wr * 64 + i * 16) * ldc
                               + bn + wc * 64 + j * 16;
                wmma::store_matrix_sync(dst, acc[i][j], ldc, wmma::mem_row_major);
            }
    } else {
        // bias + softplus epilogue via per-warp smem staging (reuse sA)
        __syncthreads();
        float* stage = reinterpret_cast<float*>(&sA[0][0][0]) + warp * 256;
        const int lane = tid & 31;
#pragma unroll
        for (int i = 0; i < 4; i++)
#pragma unroll
            for (int j = 0; j < 4; j++) {
                wmma::store_matrix_sync(stage, acc[i][j], 16, wmma::mem_row_major);
                __syncwarp();
#pragma unroll
                for (int e = 0; e < 8; e++) {
                    const int idx = lane * 8 + e;
                    const int r = idx >> 4, c = idx & 15;
                    const int gcol = bn + wc * 64 + j * 16 + c;
                    float v = stage[idx] + bias[gcol];
                    v = (v > 20.f) ? v : log1pf(expf(v));
                    C[(size_t)(bm + wr * 64 + i * 16 + r) * ldc + gcol] = v;
                }
                __syncwarp();
            }
    }
}

// ---------------- depthwise causal conv (k=4) + SiLU (fp32 + fp16 out) --------
__global__ void conv_silu_kernel(const float* __restrict__ xz,
                                 const float* __restrict__ cw,
                                 const float* __restrict__ cb,
                                 float* __restrict__ xs,
                                 __half* __restrict__ xsh)
{
    const int idx = blockIdx.x * blockDim.x + threadIdx.x;
    if (idx >= NTOK * DINNER) return;
    const int d   = idx & (DINNER - 1);
    const int tok = idx >> 11;
    const int l   = tok & (SEQLEN - 1);

    float acc = cb[d];
    const float w0 = cw[d * 4 + 0];
    const float w1 = cw[d * 4 + 1];
    const float w2 = cw[d * 4 + 2];
    const float w3 = cw[d * 4 + 3];
    if (l >= 3) acc += w0 * xz[(size_t)(tok - 3) * (2 * DINNER) + d];
    if (l >= 2) acc += w1 * xz[(size_t)(tok - 2) * (2 * DINNER) + d];
    if (l >= 1) acc += w2 * xz[(size_t)(tok - 1) * (2 * DINNER) + d];
    acc += w3 * xz[(size_t)tok * (2 * DINNER) + d];

    const float v = acc / (1.f + __expf(-acc));
    xs[idx]  = v;
    xsh[idx] = __float2half_rn(v);
}

// ---------------- split-K reduction: part[8] -> xp fp32 + xph fp16 (dt cols) --
__global__ void reduce8_kernel(const float* __restrict__ part,
                               float* __restrict__ xp,
                               __half* __restrict__ xph)
{
    const int i = blockIdx.x * blockDim.x + threadIdx.x;
    if (i >= NTOK * XPP) return;
    float s = 0.f;
#pragma unroll
    for (int k = 0; k < 8; k++) s += part[(size_t)k * (NTOK * XPP) + i];
    xp[i] = s;
    const int col = i & 127;
    if (col < DTRANK) xph[(size_t)(i >> 7) * DTRANK + col] = __float2half_rn(s);
}

// ---------------- selective scan + skip + gate (cp.async double-buffered) -----
#define STT 32
#define HCP 17

__global__ void __launch_bounds__(128)
scan_kernel(const float* __restrict__ delta,
            const float* __restrict__ xs,
            const float* __restrict__ xp,
            const float* __restrict__ xz,
            const float* __restrict__ A_log,
            const float* __restrict__ Dpar,
            __half* __restrict__ y)
{
    __shared__ float sB[2][STT][16];
    __shared__ float sC[2][STT][16];
    __shared__ float sd[2][STT][8];
    __shared__ float sx[2][STT][8];
    __shared__ float szr[2][STT][8];
    __shared__ float sHC[STT][8 * HCP];
    __shared__ float sDp[8];

    const int b    = blockIdx.y;
    const int d0   = blockIdx.x * 8;
    const int tid  = threadIdx.x;
    const int lane = tid & 31;
    const int warp = tid >> 5;
    const int grp  = lane >> 4;
    const int n    = lane & 15;
    const int ch   = warp * 2 + grp;
    const int d    = d0 + ch;

    const float An = -__expf(A_log[d * DSTATE + n]);
    if (tid < 8) sDp[tid] = Dpar[d0 + tid];
    float h = 0.f;

    const int T = SEQLEN / STT;

    auto stage = [&](int buf, int l0) {
#pragma unroll
        for (int i = tid; i < STT * 8; i += 128) {
            const int t = i >> 3, j = i & 7;
            const float* row = xp + (size_t)(b * SEQLEN + l0 + t) * XPP + DTRANK;
            if (j < 4) cp_async16(&sB[buf][t][j * 4], row + j * 4);
            else       cp_async16(&sC[buf][t][(j - 4) * 4], row + DSTATE + (j - 4) * 4);
        }
#pragma unroll
        for (int i = tid; i < STT * 2; i += 128) {
            const int t = i >> 1, c4 = (i & 1) * 4;
            const size_t tok = (size_t)(b * SEQLEN + l0 + t);
            cp_async16(&sd[buf][t][c4],  delta + tok * DINNER + d0 + c4);
            cp_async16(&sx[buf][t][c4],  xs    + tok * DINNER + d0 + c4);
            cp_async16(&szr[buf][t][c4], xz + tok * (2 * DINNER) + DINNER + d0 + c4);
        }
    };

    stage(0, 0);
    cp_async_commit();

    for (int ti = 0; ti < T; ti++) {
        if (ti + 1 < T) stage((ti + 1) & 1, (ti + 1) * STT);
        cp_async_commit();

        cp_async_wait<1>();
        __syncthreads();

        const int buf = ti & 1;
        const int l0  = ti * STT;

#pragma unroll 8
        for (int t = 0; t < STT; t++) {
            const float dt = sd[buf][t][ch];
            const float xt = sx[buf][t][ch];
            const float dA = __expf(dt * An);
            h = fmaf(dA, h, dt * xt * sB[buf][t][n]);
            sHC[t][ch * HCP + n] = h * sC[buf][t][n];
        }
        __syncthreads();

#pragma unroll
        for (int o = tid; o < STT * 8; o += 128) {
            const int t = o >> 3, c = o & 7;
            const float* p = &sHC[t][c * HCP];
            float s = 0.f;
#pragma unroll
            for (int j = 0; j < 16; j++) s += p[j];
            const float zz = szr[buf][t][c];
            const float zs = zz / (1.f + __expf(-zz));
            const float val = (s + sDp[c] * sx[buf][t][c]) * zs;
            y[(size_t)(b * SEQLEN + l0 + t) * DINNER + d0 + c] = __float2half_rn(val);
        }
        __syncthreads();
    }
}

// ---------------- launcher ----------------
extern "C" void kernel_launch(void* const* d_in, const int* in_sizes, int n_in,
                              void* d_out, int out_size)
{
    const float* x       = (const float*)d_in[0];
    const float* W_in    = (const float*)d_in[1];
    const float* conv_w  = (const float*)d_in[2];
    const float* conv_b  = (const float*)d_in[3];
    const float* W_xproj = (const float*)d_in[4];
    const float* W_dt    = (const float*)d_in[5];
    const float* b_dt    = (const float*)d_in[6];
    const float* A_log   = (const float*)d_in[7];
    const float* Dpar    = (const float*)d_in[8];
    const float* W_out   = (const float*)d_in[9];
    float* out = (float*)d_out;

    float *xz, *xs, *xp, *delta, *part;
    __half *xh, *winh, *wouth, *yh, *xsh, *xph, *wxh, *wdth;
    cudaGetSymbolAddress((void**)&xz,    g_xz);
    cudaGetSymbolAddress((void**)&xs,    g_xs);
    cudaGetSymbolAddress((void**)&xsh,   g_xsh);
    cudaGetSymbolAddress((void**)&xp,    g_xp);
    cudaGetSymbolAddress((void**)&xph,   g_xph);
    cudaGetSymbolAddress((void**)&delta, g_delta);
    cudaGetSymbolAddress((void**)&part,  g_part);
    cudaGetSymbolAddress((void**)&xh,    g_xh);
    cudaGetSymbolAddress((void**)&winh,  g_winh);
    cudaGetSymbolAddress((void**)&wouth, g_wouth);
    cudaGetSymbolAddress((void**)&wxh,   g_wxh);
    cudaGetSymbolAddress((void**)&wdth,  g_wdth);
    cudaGetSymbolAddress((void**)&yh,    g_yh);

    // prepass: fp16 conversions
    {
        const int n1 = NTOK * DMODEL / 4;
        f2h_kernel<<<(n1 + 255) / 256, 256>>>((const float4*)x, (__half2*)xh, n1);
        const int n2 = DMODEL * 2 * DINNER / 4;
        f2h_kernel<<<(n2 + 255) / 256, 256>>>((const float4*)W_in, (__half2*)winh, n2);
        const int n3 = DINNER * DMODEL / 4;
        f2h_kernel<<<(n3 + 255) / 256, 256>>>((const float4*)W_out, (__half2*)wouth, n3);
        const int n4 = DTRANK * DINNER / 4;
        f2h_kernel<<<(n4 + 255) / 256, 256>>>((const float4*)W_dt, (__half2*)wdth, n4);
        padw_kernel<<<(DINNER * XPP + 255) / 256, 256>>>(W_xproj, wxh);
    }

    // G1: xz = x @ W_in  (4096x1024)@(1024x4096)
    gemm_h<0><<<dim3((2 * DINNER) / 128, NTOK / 128, 1), 128>>>(
        xh, DMODEL, winh, 2 * DINNER, xz, 2 * DINNER, DMODEL, nullptr, 0);

    // conv + SiLU -> xs (fp32) + xsh (fp16)
    conv_silu_kernel<<<(NTOK * DINNER) / 256, 256>>>(xz, conv_w, conv_b, xs, xsh);

    // G2 (fp16 TC, split-K=8): part = xs @ W_xproj_pad   (4096x2048)@(2048x128)
    gemm_h<0><<<dim3(1, NTOK / 128, 8), 128>>>(
        xsh, DINNER, wxh, XPP, part, XPP, DINNER / 8, nullptr,
        (long long)NTOK * XPP);
    reduce8_kernel<<<(NTOK * XPP + 255) / 256, 256>>>(part, xp, xph);

    // G3 (fp16 TC): delta = softplus(xph @ W_dt + b_dt)   (4096x64)@(64x2048)
    gemm_h<1><<<dim3(DINNER / 128, NTOK / 128, 1), 128>>>(
        xph, DTRANK, wdth, DINNER, delta, DINNER, DTRANK, b_dt, 0);

    // selective scan + D*x skip + silu(z) gate -> yh (fp16)
    scan_kernel<<<dim3(DINNER / 8, BATCH), 128>>>(
        delta, xs, xp, xz, A_log, Dpar, yh);

    // G4: out = y @ W_out  (4096x2048)@(2048x1024)
    gemm_h<0><<<dim3(DMODEL / 128, NTOK / 128, 1), 128>>>(
        yh, DINNER, wouth, DMODEL, out, DMODEL, DINNER, nullptr, 0);
}

// round 15
// speedup vs baseline: 3.2631x; 1.0826x over previous
#include <cuda_runtime.h>
#include <cuda_fp16.h>
#include <math.h>
#include <stdint.h>
#include <mma.h>

using namespace nvcuda;

// ---------------- problem constants ----------------
#define BATCH   2
#define SEQLEN  2048
#define DMODEL  1024
#define DINNER  2048
#define DSTATE  16
#define DTRANK  64
#define NTOK    (BATCH * SEQLEN)           // 4096
#define XPW     96                         // logical width of xproj output
#define XPP     128                        // padded width (fp16 TC friendly)

// ---------------- scratch (device globals; no cudaMalloc allowed) ----------------
__device__ float  g_xz[NTOK * 2 * DINNER];       // (4096, 4096): xi | z
__device__ __half g_xsh[NTOK * DINNER];          // conv+silu output (fp16)
__device__ float  g_xp[NTOK * XPP];              // dt | B | C (padded to 128)
__device__ __half g_xph[NTOK * DTRANK];          // dt columns in fp16 (G3 A)
__device__ float  g_delta[NTOK * DINNER];        // softplus(dt @ W_dt + b_dt)
__device__ float  g_part[8 * NTOK * XPP];        // split-K partials for G2
__device__ __half g_xh[NTOK * DMODEL];           // x in fp16
__device__ __half g_winh[DMODEL * 2 * DINNER];   // W_in in fp16
__device__ __half g_wouth[DINNER * DMODEL];      // W_out in fp16
__device__ __half g_wxh[DINNER * XPP];           // W_xproj fp16, zero-padded
__device__ __half g_wdth[DTRANK * DINNER];       // W_dt in fp16
__device__ __half g_yh[NTOK * DINNER];           // gated scan output in fp16

// ---------------- cp.async helpers ----------------
__device__ __forceinline__ void cp_async16(void* smem_dst, const void* gmem_src) {
    unsigned saddr = (unsigned)__cvta_generic_to_shared(smem_dst);
    asm volatile("cp.async.cg.shared.global [%0], [%1], 16;\n" :: "r"(saddr), "l"(gmem_src));
}
__device__ __forceinline__ void cp_async_commit() {
    asm volatile("cp.async.commit_group;\n" ::);
}
template <int N>
__device__ __forceinline__ void cp_async_wait() {
    asm volatile("cp.async.wait_group %0;\n" :: "n"(N));
}

// ---------------- fused prepass: all fp32->fp16 conversions in one launch ------
#define PRE_N0 (NTOK * DMODEL / 4)            // x        (float4 units)
#define PRE_N1 (DMODEL * 2 * DINNER / 4)      // W_in
#define PRE_N2 (DINNER * DMODEL / 4)          // W_out
#define PRE_N3 (DTRANK * DINNER / 4)          // W_dt
#define PRE_N4 (DINNER * XPP)                 // W_xproj pad (half units)
#define PRE_TOTAL (PRE_N0 + PRE_N1 + PRE_N2 + PRE_N3 + PRE_N4)

__global__ void prepass_kernel(const float4* __restrict__ x,
                               const float4* __restrict__ W_in,
                               const float4* __restrict__ W_out,
                               const float4* __restrict__ W_dt,
                               const float*  __restrict__ W_xproj,
                               __half2* __restrict__ xh,
                               __half2* __restrict__ winh,
                               __half2* __restrict__ wouth,
                               __half2* __restrict__ wdth,
                               __half*  __restrict__ wxh)
{
    int i = blockIdx.x * blockDim.x + threadIdx.x;
    if (i >= PRE_TOTAL) return;
    const float4* src = nullptr;
    __half2* dst = nullptr;
    if (i < PRE_N0) { src = x; dst = xh; }
    else if ((i -= PRE_N0) < PRE_N1) { src = W_in; dst = winh; }
    else if ((i -= PRE_N1) < PRE_N2) { src = W_out; dst = wouth; }
    else if ((i -= PRE_N2) < PRE_N3) { src = W_dt; dst = wdth; }
    else {
        i -= PRE_N3;
        const int r = i >> 7, c = i & 127;
        wxh[i] = (c < XPW) ? __float2half_rn(W_xproj[r * XPW + c])
                           : __float2half_rn(0.f);
        return;
    }
    float4 v = src[i];
    dst[2 * i + 0] = __floats2half2_rn(v.x, v.y);
    dst[2 * i + 1] = __floats2half2_rn(v.z, v.w);
}

// ---------------- FP16 tensor-core GEMM (proven R10 config + split-K + epi) ----
#define LDA_H  24
#define LDB_H  136

template <int EPI>
__global__ void __launch_bounds__(128, 2)
gemm_h(const __half* __restrict__ A, int lda,
       const __half* __restrict__ B, int ldb,
       float* __restrict__ C, int ldc, int Kslice,
       const float* __restrict__ bias, long long c_slice_stride)
{
    __shared__ __half sA[3][128][LDA_H];
    __shared__ __half sB[3][16][LDB_H];

    const int bm  = blockIdx.y * 128;
    const int bn  = blockIdx.x * 128;
    const int tid = threadIdx.x;
    const int warp = tid >> 5;
    const int wr = warp >> 1;
    const int wc = warp & 1;

    A += blockIdx.z * Kslice;
    B += (size_t)blockIdx.z * Kslice * ldb;
    C += (long long)blockIdx.z * c_slice_stride;

    wmma::fragment<wmma::accumulator, 16, 16, 16, float> acc[4][4];
#pragma unroll
    for (int i = 0; i < 4; i++)
#pragma unroll
        for (int j = 0; j < 4; j++) wmma::fill_fragment(acc[i][j], 0.f);

    const int a_r0 = tid >> 1;
    const int a_h  = (tid & 1) * 8;
    const int b_r0 = tid >> 4;
    const int b_h  = (tid & 15) * 8;

    const int T = Kslice >> 4;

    auto load_stage = [&](int s, int t) {
        const __half* gA = A + (size_t)bm * lda + t * 16;
        cp_async16(&sA[s][a_r0][a_h],      gA + (size_t)a_r0 * lda + a_h);
        cp_async16(&sA[s][a_r0 + 64][a_h], gA + (size_t)(a_r0 + 64) * lda + a_h);
        const __half* gB = B + (size_t)(t * 16) * ldb + bn;
        cp_async16(&sB[s][b_r0][b_h],     gB + (size_t)b_r0 * ldb + b_h);
        cp_async16(&sB[s][b_r0 + 8][b_h], gB + (size_t)(b_r0 + 8) * ldb + b_h);
        cp_async_commit();
    };

    load_stage(0, 0);
    if (T > 1) load_stage(1, 1); else cp_async_commit();

    for (int t = 0; t < T; t++) {
        cp_async_wait<1>();
        __syncthreads();

        if (t + 2 < T) load_stage((t + 2) % 3, t + 2);
        else           cp_async_commit();

        const int s = t % 3;
        wmma::fragment<wmma::matrix_a, 16, 16, 16, __half, wmma::row_major> af[4];
        wmma::fragment<wmma::matrix_b, 16, 16, 16, __half, wmma::row_major> bf[4];
#pragma unroll
        for (int i = 0; i < 4; i++)
            wmma::load_matrix_sync(af[i], &sA[s][wr * 64 + i * 16][0], LDA_H);
#pragma unroll
        for (int j = 0; j < 4; j++)
            wmma::load_matrix_sync(bf[j], &sB[s][0][wc * 64 + j * 16], LDB_H);
#pragma unroll
        for (int i = 0; i < 4; i++)
#pragma unroll
            for (int j = 0; j < 4; j++)
                wmma::mma_sync(acc[i][j], af[i], bf[j], acc[i][j]);
    }

    if (EPI == 0) {
#pragma unroll
        for (int i = 0; i < 4; i++)
#pragma unroll
            for (int j = 0; j < 4; j++) {
                float* dst = C + (size_t)(bm + wr * 64 + i * 16) * ldc
                               + bn + wc * 64 + j * 16;
                wmma::store_matrix_sync(dst, acc[i][j], ldc, wmma::mem_row_major);
            }
    } else {
        __syncthreads();
        float* stage = reinterpret_cast<float*>(&sA[0][0][0]) + warp * 256;
        const int lane = tid & 31;
#pragma unroll
        for (int i = 0; i < 4; i++)
#pragma unroll
            for (int j = 0; j < 4; j++) {
                wmma::store_matrix_sync(stage, acc[i][j], 16, wmma::mem_row_major);
                __syncwarp();
#pragma unroll
                for (int e = 0; e < 8; e++) {
                    const int idx = lane * 8 + e;
                    const int r = idx >> 4, c = idx & 15;
                    const int gcol = bn + wc * 64 + j * 16 + c;
                    float v = stage[idx] + bias[gcol];
                    v = (v > 20.f) ? v : log1pf(expf(v));
                    C[(size_t)(bm + wr * 64 + i * 16 + r) * ldc + gcol] = v;
                }
                __syncwarp();
            }
    }
}

// ---------------- depthwise causal conv (k=4) + SiLU: 4 tokens/thread ---------
// Window reuse: 7 loads per 4 outputs. Token quads never straddle batches.
__global__ void conv_silu_kernel(const float* __restrict__ xz,
                                 const float* __restrict__ cw,
                                 const float* __restrict__ cb,
                                 __half* __restrict__ xsh)
{
    const int idx = blockIdx.x * blockDim.x + threadIdx.x;   // NTOK/4 * DINNER
    if (idx >= (NTOK / 4) * DINNER) return;
    const int d  = idx & (DINNER - 1);
    const int tq = idx >> 11;
    const int tok0 = tq * 4;
    const bool first = ((tok0 & (SEQLEN - 1)) == 0);

    const float w0 = cw[d * 4 + 0];
    const float w1 = cw[d * 4 + 1];
    const float w2 = cw[d * 4 + 2];
    const float w3 = cw[d * 4 + 3];
    const float bb = cb[d];

    float a[7];
    const float* base = xz + (size_t)tok0 * (2 * DINNER) + d;
    if (first) { a[0] = a[1] = a[2] = 0.f; }
    else {
        a[0] = base[-3 * (2 * DINNER)];
        a[1] = base[-2 * (2 * DINNER)];
        a[2] = base[-1 * (2 * DINNER)];
    }
#pragma unroll
    for (int i = 0; i < 4; i++) a[3 + i] = base[i * (2 * DINNER)];

#pragma unroll
    for (int i = 0; i < 4; i++) {
        const float acc = bb + w0 * a[i] + w1 * a[i + 1] + w2 * a[i + 2] + w3 * a[i + 3];
        const float v = acc / (1.f + __expf(-acc));
        xsh[(size_t)(tok0 + i) * DINNER + d] = __float2half_rn(v);
    }
}

// ---------------- split-K reduction: part[8] -> xp fp32 + xph fp16 ------------
__global__ void reduce8_kernel(const float* __restrict__ part,
                               float* __restrict__ xp,
                               __half* __restrict__ xph)
{
    const int i = blockIdx.x * blockDim.x + threadIdx.x;
    if (i >= NTOK * XPP) return;
    float s = 0.f;
#pragma unroll
    for (int k = 0; k < 8; k++) s += part[(size_t)k * (NTOK * XPP) + i];
    xp[i] = s;
    const int col = i & 127;
    if (col < DTRANK) xph[(size_t)(i >> 7) * DTRANK + col] = __float2half_rn(s);
}

// ---------------- selective scan + skip + gate: 16 channels/block -------------
#define STT 32
#define HCP 17
// dynamic smem layout (floats unless noted):
//   sB  [2][STT][16]   sC [2][STT][16]   sd [2][STT][16]   szr [2][STT][16]
//   sxh [2][STT][16] (half)   sHC [STT][16*HCP]   sDp [16]
#define SCAN_SMEM (4 * (2 * STT * 16) * 4 + (2 * STT * 16) * 2 + (STT * 16 * HCP) * 4 + 64)

__global__ void __launch_bounds__(256)
scan_kernel(const float* __restrict__ delta,
            const __half* __restrict__ xsh,
            const float* __restrict__ xp,
            const float* __restrict__ xz,
            const float* __restrict__ A_log,
            const float* __restrict__ Dpar,
            __half* __restrict__ y)
{
    extern __shared__ float smem[];
    float* sB  = smem;                         // 1024
    float* sC  = sB + 2 * STT * 16;            // 1024
    float* sd  = sC + 2 * STT * 16;            // 1024
    float* szr = sd + 2 * STT * 16;            // 1024
    __half* sxh = (__half*)(szr + 2 * STT * 16);           // 1024 halves
    float* sHC = (float*)((char*)sxh + 2 * STT * 16 * 2);  // STT*16*HCP
    float* sDp = sHC + STT * 16 * HCP;                     // 16

    const int b    = blockIdx.y;
    const int d0   = blockIdx.x * 16;
    const int tid  = threadIdx.x;
    const int lane = tid & 31;
    const int warp = tid >> 5;         // 0..7
    const int grp  = lane >> 4;
    const int n    = lane & 15;
    const int ch   = warp * 2 + grp;   // 0..15
    const int d    = d0 + ch;

    const float An = -__expf(A_log[d * DSTATE + n]);
    if (tid < 16) sDp[tid] = Dpar[d0 + tid];
    float h = 0.f;

    const int T = SEQLEN / STT;

    auto stage = [&](int buf, int l0) {
        // B/C: 8 chunks per token (4 B + 4 C), 256 total -> 1 per thread
        {
            const int t = tid >> 3, j = tid & 7;
            const float* row = xp + (size_t)(b * SEQLEN + l0 + t) * XPP + DTRANK;
            if (j < 4) cp_async16(&sB[buf * 512 + t * 16 + j * 4], row + j * 4);
            else       cp_async16(&sC[buf * 512 + t * 16 + (j - 4) * 4],
                                  row + DSTATE + (j - 4) * 4);
        }
        // delta / z: 4 chunks per token each (128 items each)
        if (tid < STT * 4) {
            const int t = tid >> 2, c4 = (tid & 3) * 4;
            const size_t tok = (size_t)(b * SEQLEN + l0 + t);
            cp_async16(&sd[buf * 512 + t * 16 + c4],  delta + tok * DINNER + d0 + c4);
            cp_async16(&szr[buf * 512 + t * 16 + c4],
                       xz + tok * (2 * DINNER) + DINNER + d0 + c4);
        }
        // x (fp16): 2 chunks per token (64 items)
        if (tid < STT * 2) {
            const int t = tid >> 1, c8 = (tid & 1) * 8;
            const size_t tok = (size_t)(b * SEQLEN + l0 + t);
            cp_async16(&sxh[buf * 512 + t * 16 + c8], xsh + tok * DINNER + d0 + c8);
        }
    };

    stage(0, 0);
    cp_async_commit();

    for (int ti = 0; ti < T; ti++) {
        if (ti + 1 < T) stage((ti + 1) & 1, (ti + 1) * STT);
        cp_async_commit();

        cp_async_wait<1>();
        __syncthreads();

        const int buf = ti & 1;
        const int l0  = ti * STT;

#pragma unroll 8
        for (int t = 0; t < STT; t++) {
            const float dt = sd[buf * 512 + t * 16 + ch];
            const float xt = __half2float(sxh[buf * 512 + t * 16 + ch]);
            const float dA = __expf(dt * An);
            h = fmaf(dA, h, dt * xt * sB[buf * 512 + t * 16 + n]);
            sHC[t * (16 * HCP) + ch * HCP + n] = h * sC[buf * 512 + t * 16 + n];
        }
        __syncthreads();

        // reduce 16 states per (t, channel): 512 outputs, 2 per thread
#pragma unroll
        for (int o = tid; o < STT * 16; o += 256) {
            const int t = o >> 4, c = o & 15;
            const float* p = &sHC[t * (16 * HCP) + c * HCP];
            float s = 0.f;
#pragma unroll
            for (int j = 0; j < 16; j++) s += p[j];
            const float zz = szr[buf * 512 + t * 16 + c];
            const float zs = zz / (1.f + __expf(-zz));
            const float xt = __half2float(sxh[buf * 512 + t * 16 + c]);
            const float val = (s + sDp[c] * xt) * zs;
            y[(size_t)(b * SEQLEN + l0 + t) * DINNER + d0 + c] = __float2half_rn(val);
        }
        __syncthreads();
    }
}

// ---------------- launcher ----------------
extern "C" void kernel_launch(void* const* d_in, const int* in_sizes, int n_in,
                              void* d_out, int out_size)
{
    const float* x       = (const float*)d_in[0];
    const float* W_in    = (const float*)d_in[1];
    const float* conv_w  = (const float*)d_in[2];
    const float* conv_b  = (const float*)d_in[3];
    const float* W_xproj = (const float*)d_in[4];
    const float* W_dt    = (const float*)d_in[5];
    const float* b_dt    = (const float*)d_in[6];
    const float* A_log   = (const float*)d_in[7];
    const float* Dpar    = (const float*)d_in[8];
    const float* W_out   = (const float*)d_in[9];
    float* out = (float*)d_out;

    float *xz, *xp, *delta, *part;
    __half *xh, *winh, *wouth, *yh, *xsh, *xph, *wxh, *wdth;
    cudaGetSymbolAddress((void**)&xz,    g_xz);
    cudaGetSymbolAddress((void**)&xsh,   g_xsh);
    cudaGetSymbolAddress((void**)&xp,    g_xp);
    cudaGetSymbolAddress((void**)&xph,   g_xph);
    cudaGetSymbolAddress((void**)&delta, g_delta);
    cudaGetSymbolAddress((void**)&part,  g_part);
    cudaGetSymbolAddress((void**)&xh,    g_xh);
    cudaGetSymbolAddress((void**)&winh,  g_winh);
    cudaGetSymbolAddress((void**)&wouth, g_wouth);
    cudaGetSymbolAddress((void**)&wxh,   g_wxh);
    cudaGetSymbolAddress((void**)&wdth,  g_wdth);
    cudaGetSymbolAddress((void**)&yh,    g_yh);

    cudaFuncSetAttribute(scan_kernel, cudaFuncAttributeMaxDynamicSharedMemorySize,
                         SCAN_SMEM);

    // fused prepass
    prepass_kernel<<<(PRE_TOTAL + 255) / 256, 256>>>(
        (const float4*)x, (const float4*)W_in, (const float4*)W_out,
        (const float4*)W_dt, W_xproj,
        (__half2*)xh, (__half2*)winh, (__half2*)wouth, (__half2*)wdth, wxh);

    // G1: xz = x @ W_in  (4096x1024)@(1024x4096)
    gemm_h<0><<<dim3((2 * DINNER) / 128, NTOK / 128, 1), 128>>>(
        xh, DMODEL, winh, 2 * DINNER, xz, 2 * DINNER, DMODEL, nullptr, 0);

    // conv + SiLU -> xsh (fp16)
    conv_silu_kernel<<<((NTOK / 4) * DINNER) / 256, 256>>>(xz, conv_w, conv_b, xsh);

    // G2 (fp16 TC, split-K=8): part = xs @ W_xproj_pad
    gemm_h<0><<<dim3(1, NTOK / 128, 8), 128>>>(
        xsh, DINNER, wxh, XPP, part, XPP, DINNER / 8, nullptr,
        (long long)NTOK * XPP);
    reduce8_kernel<<<(NTOK * XPP + 255) / 256, 256>>>(part, xp, xph);

    // G3 (fp16 TC): delta = softplus(xph @ W_dt + b_dt)
    gemm_h<1><<<dim3(DINNER / 128, NTOK / 128, 1), 128>>>(
        xph, DTRANK, wdth, DINNER, delta, DINNER, DTRANK, b_dt, 0);

    // selective scan + D*x skip + silu(z) gate -> yh (fp16)
    scan_kernel<<<dim3(DINNER / 16, BATCH), 256, SCAN_SMEM>>>(
        delta, xsh, xp, xz, A_log, Dpar, yh);

    // G4: out = y @ W_out  (4096x2048)@(2048x1024)
    gemm_h<0><<<dim3(DMODEL / 128, NTOK / 128, 1), 128>>>(
        yh, DINNER, wouth, DMODEL, out, DMODEL, DINNER, nullptr, 0);
}